// round 4
// baseline (speedup 1.0000x reference)
#include <cuda_runtime.h>
#include <math.h>

#define NN 8192
#define DIN 512
#define DOUT 256

// ---------------- scratch (static device memory; no allocation) ----------------
__device__ float g_h[NN * DOUT];          // h = x@W^T, tf32-rounded (8 MB)
__device__ float g_f1[NN];
__device__ float g_f2[NN];
__device__ float g_O[2 * NN * DOUT];      // partial O per j-half (16 MB)
__device__ float g_l[2 * NN];             // partial softmax denominators

// ---------------- helpers ----------------
__device__ __forceinline__ float tf32r(float x) {
    // round-to-nearest tf32 (keep top 19 bits)
    unsigned u = __float_as_uint(x);
    u = (u + 0x1000u) & 0xFFFFE000u;
    return __uint_as_float(u);
}

// Fast exp via FMA-only range reduction + deg-4 poly + exponent splice.
// Valid for x in [-87, ~+30]; rel err ~4e-5. Avoids MUFU (64M calls!).
__device__ __forceinline__ float fexp(float x) {
    x = fmaxf(x, -87.0f);
    float j = fmaf(x, 1.4426950408889634f, 12582912.0f); // magic 1.5*2^23
    float n = j - 12582912.0f;                            // round(x*log2e)
    float f = fmaf(n, -0.693359375f, x);                  // Cody-Waite hi
    f = fmaf(n, 2.1219444e-4f, f);                        // Cody-Waite lo
    float r = fmaf(f, 0.041666668f, 0.16666667f);
    r = fmaf(r, f, 0.5f);
    r = fmaf(r, f, 1.0f);
    r = fmaf(r, f, 1.0f);                                 // e^f
    int sc = __float_as_int(j) << 23;                     // == n << 23
    return __int_as_float(__float_as_int(r) + sc);        // e^f * 2^n
}

__device__ __forceinline__ void mma_tf32(float* d, const unsigned* a,
                                         unsigned b0, unsigned b1) {
    asm volatile(
        "mma.sync.aligned.m16n8k8.row.col.f32.tf32.tf32.f32 "
        "{%0,%1,%2,%3}, {%4,%5,%6,%7}, {%8,%9}, {%0,%1,%2,%3};\n"
        : "+f"(d[0]), "+f"(d[1]), "+f"(d[2]), "+f"(d[3])
        : "r"(a[0]), "r"(a[1]), "r"(a[2]), "r"(a[3]), "r"(b0), "r"(b1));
}

// ---------------- kernel 1: h = x @ W^T (tf32-rounded output) ----------------
// grid (2, 64): blockIdx.x = 128-col block of D_OUT, blockIdx.y = 128-row block.
__global__ __launch_bounds__(256) void k_gemm_h(const float* __restrict__ x,
                                                const float* __restrict__ W) {
    __shared__ float xs[8][128];
    __shared__ float ws[8][132];
    const int tid = threadIdx.x;
    const int mb = blockIdx.y, nb = blockIdx.x;
    const int ty = tid >> 4, tx = tid & 15;      // 16x16 threads, 8x8 micro-tile
    const int lrow = tid >> 1, lhf = tid & 1;    // G->S loading role

    const float* xg = x + (size_t)(mb * 128 + lrow) * DIN + lhf * 4;
    const float* wg = W + (size_t)(nb * 128 + lrow) * DIN + lhf * 4;

    float acc[8][8];
#pragma unroll
    for (int i = 0; i < 8; i++)
#pragma unroll
        for (int j = 0; j < 8; j++) acc[i][j] = 0.0f;

    for (int kc = 0; kc < DIN / 8; kc++) {
        float4 xv = __ldg((const float4*)(xg + kc * 8));
        float4 wv = __ldg((const float4*)(wg + kc * 8));
        __syncthreads();
        xs[lhf * 4 + 0][lrow] = xv.x; xs[lhf * 4 + 1][lrow] = xv.y;
        xs[lhf * 4 + 2][lrow] = xv.z; xs[lhf * 4 + 3][lrow] = xv.w;
        ws[lhf * 4 + 0][lrow] = wv.x; ws[lhf * 4 + 1][lrow] = wv.y;
        ws[lhf * 4 + 2][lrow] = wv.z; ws[lhf * 4 + 3][lrow] = wv.w;
        __syncthreads();
#pragma unroll
        for (int k = 0; k < 8; k++) {
            float4 a0 = *(const float4*)&xs[k][ty * 8];
            float4 a1 = *(const float4*)&xs[k][ty * 8 + 4];
            float4 b0 = *(const float4*)&ws[k][tx * 8];
            float4 b1 = *(const float4*)&ws[k][tx * 8 + 4];
            float am[8] = {a0.x, a0.y, a0.z, a0.w, a1.x, a1.y, a1.z, a1.w};
            float bm[8] = {b0.x, b0.y, b0.z, b0.w, b1.x, b1.y, b1.z, b1.w};
#pragma unroll
            for (int i = 0; i < 8; i++)
#pragma unroll
                for (int j = 0; j < 8; j++)
                    acc[i][j] = fmaf(am[i], bm[j], acc[i][j]);
        }
    }
#pragma unroll
    for (int i = 0; i < 8; i++) {
        size_t o = (size_t)(mb * 128 + ty * 8 + i) * DOUT + nb * 128 + tx * 8;
        float4 v0 = make_float4(tf32r(acc[i][0]), tf32r(acc[i][1]),
                                tf32r(acc[i][2]), tf32r(acc[i][3]));
        float4 v1 = make_float4(tf32r(acc[i][4]), tf32r(acc[i][5]),
                                tf32r(acc[i][6]), tf32r(acc[i][7]));
        *(float4*)&g_h[o] = v0;
        *(float4*)&g_h[o + 4] = v1;
    }
}

// ---------------- kernel 2: f1 = h@a1, f2 = h@a2 ----------------
__global__ __launch_bounds__(256) void k_f1f2(const float* __restrict__ a1,
                                              const float* __restrict__ a2) {
    __shared__ float a1s[DOUT], a2s[DOUT];
    int tid = threadIdx.x;
    a1s[tid] = a1[tid];
    a2s[tid] = a2[tid];
    __syncthreads();
    int w = tid >> 5, lane = tid & 31;
    int row = blockIdx.x * 8 + w;
    const float* hr = g_h + (size_t)row * DOUT;
    float s1 = 0.0f, s2 = 0.0f;
#pragma unroll
    for (int q = 0; q < 8; q++) {
        float hv = hr[q * 32 + lane];
        s1 = fmaf(hv, a1s[q * 32 + lane], s1);
        s2 = fmaf(hv, a2s[q * 32 + lane], s2);
    }
#pragma unroll
    for (int off = 16; off >= 1; off >>= 1) {
        s1 += __shfl_xor_sync(0xffffffffu, s1, off);
        s2 += __shfl_xor_sync(0xffffffffu, s2, off);
    }
    if (lane == 0) { g_f1[row] = s1; g_f2[row] = s2; }
}

// ---------------- kernel 3: fused masked-softmax-numerator @ h ----------------
// grid (2, 64): blockIdx.x = j-half (4096 cols), blockIdx.y = 128-row block.
// Per CTA: accumulate O_part = sum_j exp(score)*h_j (tf32 mma), l_part = sum_j exp(score).
#define SP_STRIDE 132
#define SH_STRIDE 264
#define SMEM_FLOATS (128 * SP_STRIDE + 128 * SH_STRIDE + 128)
__global__ __launch_bounds__(256, 1) void k_attn(const float* __restrict__ adj) {
    extern __shared__ float sm[];
    float* sP = sm;                          // 128 x 132
    float* sH = sm + 128 * SP_STRIDE;        // 128 x 264
    float* f1s = sH + 128 * SH_STRIDE;       // 128

    const int tid = threadIdx.x;
    const int jh = blockIdx.x;               // j half
    const int rb = blockIdx.y;               // row block
    const int lane = tid & 31, w = tid >> 5;
    const int wm = w >> 2, wn = w & 3;       // 2 (m) x 4 (n) warp grid
    const int g = lane >> 2, tq = lane & 3;

    if (tid < 128) f1s[tid] = g_f1[rb * 128 + tid];

    float acc[4][8][4];
#pragma unroll
    for (int mt = 0; mt < 4; mt++)
#pragma unroll
        for (int nb = 0; nb < 8; nb++)
#pragma unroll
            for (int q = 0; q < 4; q++) acc[mt][nb][q] = 0.0f;

    float lsum = 0.0f;
    const float* adjb = adj + (size_t)(rb * 128) * NN;

    for (int jt = 0; jt < 32; jt++) {
        const int j0 = jh * 4096 + jt * 128;
        __syncthreads();  // previous tile's reads of sP/sH done

        // ---- stage h tile [128 x 256] -> sH (tf32 already) ----
        const float* hsrc = g_h + (size_t)j0 * DOUT;
#pragma unroll 8
        for (int i = 0; i < 32; i++) {
            int v = tid + i * 256;           // float4 index 0..8191
            int k = v >> 6;
            int n4 = (v & 63) << 2;
            *(float4*)&sH[k * SH_STRIDE + n4] =
                *(const float4*)(hsrc + k * DOUT + n4);
        }

        // ---- compute P tile: p = exp(mask(lrelu(f1+f2))) -> sP (tf32) ----
#pragma unroll 4
        for (int i = 0; i < 16; i++) {
            int v = tid + i * 256;
            int r = v >> 5;
            int c = (v & 31) << 2;
            float4 av = __ldg((const float4*)(adjb + (size_t)r * NN + j0 + c));
            float4 f2v = *(const float4*)(g_f2 + j0 + c);
            float f1v = f1s[r];
            float p[4];
            float zz[4] = {f1v + f2v.x, f1v + f2v.y, f1v + f2v.z, f1v + f2v.w};
            float aa[4] = {av.x, av.y, av.z, av.w};
#pragma unroll
            for (int q = 0; q < 4; q++) {
                float s = fmaxf(zz[q], 0.01f * zz[q]) * aa[q]; // leaky-relu * adj
                s = (s == 0.0f) ? -1e9f : s;                   // mask exact zeros
                p[q] = tf32r(fexp(s));
            }
            *(float4*)&sP[r * SP_STRIDE + c] = make_float4(p[0], p[1], p[2], p[3]);
        }
        __syncthreads();

        // ---- deterministic row-sum of P (denominator) ----
        {
            int r = tid >> 1;
            int hf0 = (tid & 1) << 6;
            const float* rowp = sP + r * SP_STRIDE + hf0;
            float s = 0.0f;
#pragma unroll
            for (int jj = 0; jj < 64; jj += 4) {
                float4 pv = *(const float4*)(rowp + jj);
                s += (pv.x + pv.y) + (pv.z + pv.w);
            }
            lsum += s;
        }

        // ---- mma: acc += P[128x128] @ H[128x256] (tf32) ----
#pragma unroll 2
        for (int kc = 0; kc < 16; kc++) {
            unsigned a[4][4];
#pragma unroll
            for (int mt = 0; mt < 4; mt++) {
                const float* base =
                    &sP[(wm * 64 + mt * 16 + g) * SP_STRIDE + kc * 8 + tq];
                a[mt][0] = __float_as_uint(base[0]);
                a[mt][1] = __float_as_uint(base[8 * SP_STRIDE]);
                a[mt][2] = __float_as_uint(base[4]);
                a[mt][3] = __float_as_uint(base[8 * SP_STRIDE + 4]);
            }
#pragma unroll
            for (int nb = 0; nb < 8; nb++) {
                const float* bb =
                    &sH[(kc * 8 + tq) * SH_STRIDE + wn * 64 + nb * 8 + g];
                unsigned b0 = __float_as_uint(bb[0]);
                unsigned b1 = __float_as_uint(bb[4 * SH_STRIDE]);
#pragma unroll
                for (int mt = 0; mt < 4; mt++) mma_tf32(acc[mt][nb], a[mt], b0, b1);
            }
        }
    }

    // ---- epilogue: write partial O (streaming) and partial l ----
    {
        float other = __shfl_xor_sync(0xffffffffu, lsum, 1);
        float ltot = lsum + other;
        if ((tid & 1) == 0) g_l[jh * NN + rb * 128 + (tid >> 1)] = ltot;
    }
    float* Op = g_O + (size_t)jh * NN * DOUT;
#pragma unroll
    for (int mt = 0; mt < 4; mt++) {
        int row0 = rb * 128 + wm * 64 + mt * 16 + g;
#pragma unroll
        for (int nb = 0; nb < 8; nb++) {
            int col = wn * 64 + nb * 8 + tq * 2;
            __stcg((float2*)&Op[(size_t)row0 * DOUT + col],
                   make_float2(acc[mt][nb][0], acc[mt][nb][1]));
            __stcg((float2*)&Op[(size_t)(row0 + 8) * DOUT + col],
                   make_float2(acc[mt][nb][2], acc[mt][nb][3]));
        }
    }
}

// ---------------- kernel 4: combine halves, divide, elu ----------------
__global__ __launch_bounds__(256) void k_out(float* __restrict__ out) {
    int idx = blockIdx.x * 256 + threadIdx.x;   // 0 .. 2M-1
    int row = idx >> 8;
    float linv = 1.0f / (g_l[row] + g_l[NN + row]);
    float o = (g_O[idx] + g_O[NN * DOUT + idx]) * linv;
    out[idx] = (o > 0.0f) ? o : expm1f(o);
}

// ---------------- launch ----------------
extern "C" void kernel_launch(void* const* d_in, const int* in_sizes, int n_in,
                              void* d_out, int out_size) {
    const float* x   = (const float*)d_in[0];   // [8192, 512]
    const float* adj = (const float*)d_in[1];   // [8192, 8192]
    const float* W   = (const float*)d_in[2];   // [256, 512]
    const float* a1  = (const float*)d_in[3];   // [256]
    const float* a2  = (const float*)d_in[4];   // [256]
    float* out = (float*)d_out;                 // [8192, 256]

    (void)in_sizes; (void)n_in; (void)out_size;
    cudaFuncSetAttribute(k_attn, cudaFuncAttributeMaxDynamicSharedMemorySize,
                         SMEM_FLOATS * (int)sizeof(float));

    k_gemm_h<<<dim3(2, 64), 256>>>(x, W);
    k_f1f2<<<NN / 8, 256>>>(a1, a2);
    k_attn<<<dim3(2, 64), 256, SMEM_FLOATS * sizeof(float)>>>(adj);
    k_out<<<(NN * DOUT) / 256, 256>>>(out);
}

// round 7
// speedup vs baseline: 1.0380x; 1.0380x over previous
#include <cuda_runtime.h>
#include <math.h>
#include <stdint.h>

#define NN 8192
#define DIN 512
#define DOUT 256

// ---------------- scratch (static device memory; no allocation) ----------------
__device__ float g_h[NN * DOUT];          // h = x@W^T, tf32-rounded (8 MB)
__device__ float g_f1[NN];
__device__ float g_f2[NN];
__device__ float g_O[2 * NN * DOUT];      // partial O per j-half (16 MB)
__device__ float g_l[2 * NN];             // partial softmax denominators

// ---------------- helpers ----------------
__device__ __forceinline__ float tf32r(float x) {
    // round-to-nearest tf32 (keep top 19 bits)
    unsigned u = __float_as_uint(x);
    u = (u + 0x1000u) & 0xFFFFE000u;
    return __uint_as_float(u);
}

// Fast exp via FMA-only range reduction + deg-4 poly + exponent splice.
// Input here is lrelu(f1+f2) in roughly [-0.2, 20]; rel err ~4e-5. No MUFU.
__device__ __forceinline__ float fexp(float x) {
    float j = fmaf(x, 1.4426950408889634f, 12582912.0f); // magic 1.5*2^23
    float n = j - 12582912.0f;                            // round(x*log2e)
    float f = fmaf(n, -0.693359375f, x);                  // Cody-Waite hi
    f = fmaf(n, 2.1219444e-4f, f);                        // Cody-Waite lo
    float r = fmaf(f, 0.041666668f, 0.16666667f);
    r = fmaf(r, f, 0.5f);
    r = fmaf(r, f, 1.0f);
    r = fmaf(r, f, 1.0f);                                 // e^f
    int sc = __float_as_int(j) << 23;                     // == n << 23
    return __int_as_float(__float_as_int(r) + sc);        // e^f * 2^n
}

__device__ __forceinline__ void mma_tf32(float* d, const unsigned* a,
                                         unsigned b0, unsigned b1) {
    asm volatile(
        "mma.sync.aligned.m16n8k8.row.col.f32.tf32.tf32.f32 "
        "{%0,%1,%2,%3}, {%4,%5,%6,%7}, {%8,%9}, {%0,%1,%2,%3};\n"
        : "+f"(d[0]), "+f"(d[1]), "+f"(d[2]), "+f"(d[3])
        : "r"(a[0]), "r"(a[1]), "r"(a[2]), "r"(a[3]), "r"(b0), "r"(b1));
}

// ---------------- kernel 1: h = x @ W^T (tf32-rounded output) ----------------
// grid (2, 64): blockIdx.x = 128-col block of D_OUT, blockIdx.y = 128-row block.
__global__ __launch_bounds__(256) void k_gemm_h(const float* __restrict__ x,
                                                const float* __restrict__ W) {
    __shared__ float xs[8][128];
    __shared__ float ws[8][132];
    const int tid = threadIdx.x;
    const int mb = blockIdx.y, nb = blockIdx.x;
    const int ty = tid >> 4, tx = tid & 15;      // 16x16 threads, 8x8 micro-tile
    const int lrow = tid >> 1, lhf = tid & 1;    // G->S loading role

    const float* xg = x + (size_t)(mb * 128 + lrow) * DIN + lhf * 4;
    const float* wg = W + (size_t)(nb * 128 + lrow) * DIN + lhf * 4;

    float acc[8][8];
#pragma unroll
    for (int i = 0; i < 8; i++)
#pragma unroll
        for (int j = 0; j < 8; j++) acc[i][j] = 0.0f;

    for (int kc = 0; kc < DIN / 8; kc++) {
        float4 xv = __ldg((const float4*)(xg + kc * 8));
        float4 wv = __ldg((const float4*)(wg + kc * 8));
        __syncthreads();
        xs[lhf * 4 + 0][lrow] = xv.x; xs[lhf * 4 + 1][lrow] = xv.y;
        xs[lhf * 4 + 2][lrow] = xv.z; xs[lhf * 4 + 3][lrow] = xv.w;
        ws[lhf * 4 + 0][lrow] = wv.x; ws[lhf * 4 + 1][lrow] = wv.y;
        ws[lhf * 4 + 2][lrow] = wv.z; ws[lhf * 4 + 3][lrow] = wv.w;
        __syncthreads();
#pragma unroll
        for (int k = 0; k < 8; k++) {
            float4 a0 = *(const float4*)&xs[k][ty * 8];
            float4 a1 = *(const float4*)&xs[k][ty * 8 + 4];
            float4 b0 = *(const float4*)&ws[k][tx * 8];
            float4 b1 = *(const float4*)&ws[k][tx * 8 + 4];
            float am[8] = {a0.x, a0.y, a0.z, a0.w, a1.x, a1.y, a1.z, a1.w};
            float bm[8] = {b0.x, b0.y, b0.z, b0.w, b1.x, b1.y, b1.z, b1.w};
#pragma unroll
            for (int i = 0; i < 8; i++)
#pragma unroll
                for (int j = 0; j < 8; j++)
                    acc[i][j] = fmaf(am[i], bm[j], acc[i][j]);
        }
    }
#pragma unroll
    for (int i = 0; i < 8; i++) {
        size_t o = (size_t)(mb * 128 + ty * 8 + i) * DOUT + nb * 128 + tx * 8;
        float4 v0 = make_float4(tf32r(acc[i][0]), tf32r(acc[i][1]),
                                tf32r(acc[i][2]), tf32r(acc[i][3]));
        float4 v1 = make_float4(tf32r(acc[i][4]), tf32r(acc[i][5]),
                                tf32r(acc[i][6]), tf32r(acc[i][7]));
        *(float4*)&g_h[o] = v0;
        *(float4*)&g_h[o + 4] = v1;
    }
}

// ---------------- kernel 2: f1 = h@a1, f2 = h@a2 ----------------
__global__ __launch_bounds__(256) void k_f1f2(const float* __restrict__ a1,
                                              const float* __restrict__ a2) {
    __shared__ float a1s[DOUT], a2s[DOUT];
    int tid = threadIdx.x;
    a1s[tid] = a1[tid];
    a2s[tid] = a2[tid];
    __syncthreads();
    int w = tid >> 5, lane = tid & 31;
    int row = blockIdx.x * 8 + w;
    const float* hr = g_h + (size_t)row * DOUT;
    float s1 = 0.0f, s2 = 0.0f;
#pragma unroll
    for (int q = 0; q < 8; q++) {
        float hv = hr[q * 32 + lane];
        s1 = fmaf(hv, a1s[q * 32 + lane], s1);
        s2 = fmaf(hv, a2s[q * 32 + lane], s2);
    }
#pragma unroll
    for (int off = 16; off >= 1; off >>= 1) {
        s1 += __shfl_xor_sync(0xffffffffu, s1, off);
        s2 += __shfl_xor_sync(0xffffffffu, s2, off);
    }
    if (lane == 0) { g_f1[row] = s1; g_f2[row] = s2; }
}

// ---------------- kernel 3: fused masked-softmax-numerator @ h ----------------
// grid (2, 64): blockIdx.x = j-half (4096 cols), blockIdx.y = 128-row block.
// 512 threads, 16 warps in a 4x4 grid; each warp owns a 32x64 output tile.
#define SP_STRIDE 132
#define SH_STRIDE 264
#define SMEM_FLOATS (128 * SP_STRIDE + 128 * SH_STRIDE + 128)
__global__ __launch_bounds__(512, 1) void k_attn(const float* __restrict__ adj) {
    extern __shared__ float sm[];
    float* sP = sm;                          // 128 x 132
    float* sH = sm + 128 * SP_STRIDE;        // 128 x 264
    float* f1s = sH + 128 * SH_STRIDE;       // 128

    const int tid = threadIdx.x;
    const int jh = blockIdx.x;               // j half
    const int rb = blockIdx.y;               // row block
    const int lane = tid & 31, w = tid >> 5;
    const int wm = w >> 2, wn = w & 3;       // 4 (m) x 4 (n) warp grid
    const int g = lane >> 2, tq = lane & 3;

    if (tid < 128) f1s[tid] = g_f1[rb * 128 + tid];

    float acc[2][8][4];
#pragma unroll
    for (int mt = 0; mt < 2; mt++)
#pragma unroll
        for (int nb = 0; nb < 8; nb++)
#pragma unroll
            for (int q = 0; q < 4; q++) acc[mt][nb][q] = 0.0f;

    float lacc[8];
#pragma unroll
    for (int i = 0; i < 8; i++) lacc[i] = 0.0f;

    const float* adjb = adj + (size_t)(rb * 128) * NN;

    for (int jt = 0; jt < 32; jt++) {
        const int j0 = jh * 4096 + jt * 128;
        __syncthreads();  // previous tile's smem reads done (also orders f1s on jt=0)

        // ---- stage h tile [128 x 256] -> sH ----
        const float* hsrc = g_h + (size_t)j0 * DOUT;
#pragma unroll
        for (int i = 0; i < 16; i++) {
            int v = tid + i * 512;           // float4 index 0..8191
            int k = v >> 6;
            int n4 = (v & 63) << 2;
            *(float4*)&sH[k * SH_STRIDE + n4] =
                *(const float4*)(hsrc + k * DOUT + n4);
        }

        // ---- P tile + inline row-sum ----
        // Warp w, iter i covers row r = w + 16*i entirely (lane -> cols 4l..4l+3).
        float4 f2v = __ldg((const float4*)(g_f2 + j0 + 4 * lane));
#pragma unroll
        for (int i = 0; i < 8; i++) {
            int r = w + 16 * i;
            float f1v = f1s[r];
            float4 av = __ldg((const float4*)(adjb + (size_t)r * NN + j0 + 4 * lane));
            float z0 = f1v + f2v.x, z1 = f1v + f2v.y;
            float z2 = f1v + f2v.z, z3 = f1v + f2v.w;
            float p0 = av.x * tf32r(fexp(fmaxf(z0, 0.01f * z0)));
            float p1 = av.y * tf32r(fexp(fmaxf(z1, 0.01f * z1)));
            float p2 = av.z * tf32r(fexp(fmaxf(z2, 0.01f * z2)));
            float p3 = av.w * tf32r(fexp(fmaxf(z3, 0.01f * z3)));
            *(float4*)&sP[r * SP_STRIDE + 4 * lane] =
                make_float4(p0, p1, p2, p3);
            float s = (p0 + p1) + (p2 + p3);
#pragma unroll
            for (int off = 16; off >= 1; off >>= 1)
                s += __shfl_xor_sync(0xffffffffu, s, off);
            lacc[i] += s;                    // deterministic fixed-order sum
        }
        __syncthreads();

        // ---- mma: acc += P[128x128] @ H[128x256] (tf32) ----
#pragma unroll
        for (int kc = 0; kc < 16; kc++) {
            unsigned a[2][4];
#pragma unroll
            for (int mt = 0; mt < 2; mt++) {
                const float* base =
                    &sP[(wm * 32 + mt * 16 + g) * SP_STRIDE + kc * 8 + tq];
                a[mt][0] = __float_as_uint(base[0]);
                a[mt][1] = __float_as_uint(base[8 * SP_STRIDE]);
                a[mt][2] = __float_as_uint(base[4]);
                a[mt][3] = __float_as_uint(base[8 * SP_STRIDE + 4]);
            }
#pragma unroll
            for (int nb = 0; nb < 8; nb++) {
                const float* bb =
                    &sH[(kc * 8 + tq) * SH_STRIDE + wn * 64 + nb * 8 + g];
                unsigned b0 = __float_as_uint(bb[0]);
                unsigned b1 = __float_as_uint(bb[4 * SH_STRIDE]);
#pragma unroll
                for (int mt = 0; mt < 2; mt++) mma_tf32(acc[mt][nb], a[mt], b0, b1);
            }
        }
    }

    // ---- epilogue: partial l (lane 0 of each warp holds full row sums) ----
#pragma unroll
    for (int i = 0; i < 8; i++)
        if (lane == 0) g_l[jh * NN + rb * 128 + w + 16 * i] = lacc[i];

    // ---- epilogue: partial O (normal stores; stays L2-resident for k_out) ----
    float* Op = g_O + (size_t)jh * NN * DOUT;
#pragma unroll
    for (int mt = 0; mt < 2; mt++) {
        int row0 = rb * 128 + wm * 32 + mt * 16 + g;
#pragma unroll
        for (int nb = 0; nb < 8; nb++) {
            int col = wn * 64 + nb * 8 + tq * 2;
            *(float2*)&Op[(size_t)row0 * DOUT + col] =
                make_float2(acc[mt][nb][0], acc[mt][nb][1]);
            *(float2*)&Op[(size_t)(row0 + 8) * DOUT + col] =
                make_float2(acc[mt][nb][2], acc[mt][nb][3]);
        }
    }
}

// ---------------- kernel 4: combine halves, divide, elu ----------------
__global__ __launch_bounds__(256) void k_out(float* __restrict__ out) {
    int idx = blockIdx.x * 256 + threadIdx.x;   // 0 .. 2M-1
    int row = idx >> 8;
    float linv = 1.0f / (g_l[row] + g_l[NN + row]);
    float o = (g_O[idx] + g_O[NN * DOUT + idx]) * linv;
    out[idx] = (o > 0.0f) ? o : expm1f(o);
}

// ---------------- launch ----------------
extern "C" void kernel_launch(void* const* d_in, const int* in_sizes, int n_in,
                              void* d_out, int out_size) {
    const float* x   = (const float*)d_in[0];   // [8192, 512]
    const float* adj = (const float*)d_in[1];   // [8192, 8192]
    const float* W   = (const float*)d_in[2];   // [256, 512]
    const float* a1  = (const float*)d_in[3];   // [256]
    const float* a2  = (const float*)d_in[4];   // [256]
    float* out = (float*)d_out;                 // [8192, 256]

    (void)in_sizes; (void)n_in; (void)out_size;
    cudaFuncSetAttribute(k_attn, cudaFuncAttributeMaxDynamicSharedMemorySize,
                         SMEM_FLOATS * (int)sizeof(float));

    k_gemm_h<<<dim3(2, 64), 256>>>(x, W);
    k_f1f2<<<NN / 8, 256>>>(a1, a2);
    k_attn<<<dim3(2, 64), 512, SMEM_FLOATS * sizeof(float)>>>(adj);
    k_out<<<(NN * DOUT) / 256, 256>>>(out);
}

// round 9
// speedup vs baseline: 1.4093x; 1.3577x over previous
#include <cuda_runtime.h>
#include <cuda_fp16.h>
#include <math.h>
#include <stdint.h>

#define NN 8192
#define DIN 512
#define DOUT 256

// ---------------- scratch (static device memory; no allocation) ----------------
__device__ float g_h[NN * DOUT];            // h = x@W^T, fp32 (for f1/f2)
__device__ __half g_hT[DOUT * NN];          // h transposed [n][j], fp16 (MMA B operand)
__device__ float g_f1[NN];
__device__ float g_f2[NN];
__device__ float g_m2;                      // global max of f2
__device__ float g_O[2 * NN * DOUT];        // partial O per j-half (16 MB)
__device__ float g_l[2 * NN];               // partial softmax denominators

// ---------------- helpers ----------------
// Fast exp via FMA-only range reduction + deg-4 poly + exponent splice.
// Input here is (lrelu(z) - c) in about [-30, 0]; rel err ~4e-5. No MUFU.
__device__ __forceinline__ float fexp(float x) {
    float j = fmaf(x, 1.4426950408889634f, 12582912.0f); // magic 1.5*2^23
    float n = j - 12582912.0f;                            // round(x*log2e)
    float f = fmaf(n, -0.693359375f, x);                  // Cody-Waite hi
    f = fmaf(n, 2.1219444e-4f, f);                        // Cody-Waite lo
    float r = fmaf(f, 0.041666668f, 0.16666667f);
    r = fmaf(r, f, 0.5f);
    r = fmaf(r, f, 1.0f);
    r = fmaf(r, f, 1.0f);                                 // e^f
    int sc = __float_as_int(j) << 23;                     // == n << 23
    return __int_as_float(__float_as_int(r) + sc);        // e^f * 2^n
}

// fp16 mma m16n8k16: A 4 regs (8 f16), B 2 regs (4 f16), C/D 4 f32.
__device__ __forceinline__ void mma_f16(float* d, const unsigned* a,
                                        unsigned b0, unsigned b1) {
    asm volatile(
        "mma.sync.aligned.m16n8k16.row.col.f32.f16.f16.f32 "
        "{%0,%1,%2,%3}, {%4,%5,%6,%7}, {%8,%9}, {%0,%1,%2,%3};\n"
        : "+f"(d[0]), "+f"(d[1]), "+f"(d[2]), "+f"(d[3])
        : "r"(a[0]), "r"(a[1]), "r"(a[2]), "r"(a[3]), "r"(b0), "r"(b1));
}

// ---------------- kernel 1: h = x @ W^T (fp32 + fp16-transposed copy) ----------
// grid (2, 64): blockIdx.x = 128-col block of D_OUT, blockIdx.y = 128-row block.
__global__ __launch_bounds__(256) void k_gemm_h(const float* __restrict__ x,
                                                const float* __restrict__ W) {
    __shared__ float xs[8][128];
    __shared__ float ws[8][132];
    const int tid = threadIdx.x;
    const int mb = blockIdx.y, nb = blockIdx.x;
    const int ty = tid >> 4, tx = tid & 15;      // 16x16 threads, 8x8 micro-tile
    const int lrow = tid >> 1, lhf = tid & 1;    // G->S loading role

    const float* xg = x + (size_t)(mb * 128 + lrow) * DIN + lhf * 4;
    const float* wg = W + (size_t)(nb * 128 + lrow) * DIN + lhf * 4;

    float acc[8][8];
#pragma unroll
    for (int i = 0; i < 8; i++)
#pragma unroll
        for (int j = 0; j < 8; j++) acc[i][j] = 0.0f;

    for (int kc = 0; kc < DIN / 8; kc++) {
        float4 xv = __ldg((const float4*)(xg + kc * 8));
        float4 wv = __ldg((const float4*)(wg + kc * 8));
        __syncthreads();
        xs[lhf * 4 + 0][lrow] = xv.x; xs[lhf * 4 + 1][lrow] = xv.y;
        xs[lhf * 4 + 2][lrow] = xv.z; xs[lhf * 4 + 3][lrow] = xv.w;
        ws[lhf * 4 + 0][lrow] = wv.x; ws[lhf * 4 + 1][lrow] = wv.y;
        ws[lhf * 4 + 2][lrow] = wv.z; ws[lhf * 4 + 3][lrow] = wv.w;
        __syncthreads();
#pragma unroll
        for (int k = 0; k < 8; k++) {
            float4 a0 = *(const float4*)&xs[k][ty * 8];
            float4 a1 = *(const float4*)&xs[k][ty * 8 + 4];
            float4 b0 = *(const float4*)&ws[k][tx * 8];
            float4 b1 = *(const float4*)&ws[k][tx * 8 + 4];
            float am[8] = {a0.x, a0.y, a0.z, a0.w, a1.x, a1.y, a1.z, a1.w};
            float bm[8] = {b0.x, b0.y, b0.z, b0.w, b1.x, b1.y, b1.z, b1.w};
#pragma unroll
            for (int i = 0; i < 8; i++)
#pragma unroll
                for (int j = 0; j < 8; j++)
                    acc[i][j] = fmaf(am[i], bm[j], acc[i][j]);
        }
    }
    // fp32 row-major g_h (feeds f1/f2)
#pragma unroll
    for (int i = 0; i < 8; i++) {
        size_t o = (size_t)(mb * 128 + ty * 8 + i) * DOUT + nb * 128 + tx * 8;
        *(float4*)&g_h[o] = make_float4(acc[i][0], acc[i][1], acc[i][2], acc[i][3]);
        *(float4*)&g_h[o + 4] = make_float4(acc[i][4], acc[i][5], acc[i][6], acc[i][7]);
    }
    // fp16 transposed g_hT[n][j] (MMA B operand); 8 consecutive j per store
#pragma unroll
    for (int q = 0; q < 8; q++) {
        int n = nb * 128 + tx * 8 + q;
        size_t o = (size_t)n * NN + mb * 128 + ty * 8;
        __half2 hh[4];
#pragma unroll
        for (int i = 0; i < 4; i++)
            hh[i] = __floats2half2_rn(acc[2 * i][q], acc[2 * i + 1][q]);
        *(uint4*)&g_hT[o] = *(const uint4*)hh;
    }
}

// ---------------- kernel 2: f1 = h@a1, f2 = h@a2 ----------------
__global__ __launch_bounds__(256) void k_f1f2(const float* __restrict__ a1,
                                              const float* __restrict__ a2) {
    __shared__ float a1s[DOUT], a2s[DOUT];
    int tid = threadIdx.x;
    a1s[tid] = a1[tid];
    a2s[tid] = a2[tid];
    __syncthreads();
    int w = tid >> 5, lane = tid & 31;
    int row = blockIdx.x * 8 + w;
    const float* hr = g_h + (size_t)row * DOUT;
    float s1 = 0.0f, s2 = 0.0f;
#pragma unroll
    for (int q = 0; q < 8; q++) {
        float hv = hr[q * 32 + lane];
        s1 = fmaf(hv, a1s[q * 32 + lane], s1);
        s2 = fmaf(hv, a2s[q * 32 + lane], s2);
    }
#pragma unroll
    for (int off = 16; off >= 1; off >>= 1) {
        s1 += __shfl_xor_sync(0xffffffffu, s1, off);
        s2 += __shfl_xor_sync(0xffffffffu, s2, off);
    }
    if (lane == 0) { g_f1[row] = s1; g_f2[row] = s2; }
}

// ---------------- kernel 2b: global max of f2 (order-independent) ----------------
__global__ __launch_bounds__(1024) void k_max() {
    __shared__ float red[32];
    int tid = threadIdx.x;
    float m = -1e30f;
#pragma unroll
    for (int i = 0; i < 8; i++) m = fmaxf(m, g_f2[tid + i * 1024]);
#pragma unroll
    for (int off = 16; off >= 1; off >>= 1)
        m = fmaxf(m, __shfl_xor_sync(0xffffffffu, m, off));
    if ((tid & 31) == 0) red[tid >> 5] = m;
    __syncthreads();
    if (tid < 32) {
        m = red[tid];
#pragma unroll
        for (int off = 16; off >= 1; off >>= 1)
            m = fmaxf(m, __shfl_xor_sync(0xffffffffu, m, off));
        if (tid == 0) g_m2 = m;
    }
}

// ---------------- kernel 3: fused masked-softmax-numerator @ h (fp16 mma) ----
// grid (2, 64): blockIdx.x = j-half (4096 cols), blockIdx.y = 128-row block.
// 512 threads, 16 warps in a 4x4 grid; each warp owns a 32x64 output tile.
// P is computed SHIFTED: p = adj * exp(lrelu(z) - c_r), c_r = lrelu(f1_r + max f2)
// so p in (0,1] -- fp16-safe. Both j-halves use the same c_r (global max),
// so partial l/O combine exactly in k_out.
#define SPH_STRIDE 136
#define SP_BYTES   (128 * SPH_STRIDE * 2)             // 34816
#define SH_BYTES   (256 * SPH_STRIDE * 2)             // 69632
#define F1_BYTEOFF (SP_BYTES + SH_BYTES)              // 104448
#define SMEM_BYTES (F1_BYTEOFF + 512)                 // 104960
__global__ __launch_bounds__(512, 1) void k_attn(const float* __restrict__ adj) {
    extern __shared__ __align__(16) char smraw[];
    __half* sP  = (__half*)smraw;                     // 128 x 136 (k-major rows)
    __half* sHT = (__half*)(smraw + SP_BYTES);        // 256 n-rows x 136 k
    float*  f1s = (float*)(smraw + F1_BYTEOFF);       // 128

    const int tid = threadIdx.x;
    const int jh = blockIdx.x;               // j half
    const int rb = blockIdx.y;               // row block
    const int lane = tid & 31, w = tid >> 5;
    const int wm = w >> 2, wn = w & 3;       // 4 (m) x 4 (n) warp grid
    const int g = lane >> 2, tq = lane & 3;

    if (tid < 128) f1s[tid] = g_f1[rb * 128 + tid];
    const float m2 = g_m2;

    float acc[2][8][4];
#pragma unroll
    for (int mt = 0; mt < 2; mt++)
#pragma unroll
        for (int nb = 0; nb < 8; nb++)
#pragma unroll
            for (int q = 0; q < 4; q++) acc[mt][nb][q] = 0.0f;

    float lacc[8];                           // per-lane partial row sums
#pragma unroll
    for (int i = 0; i < 8; i++) lacc[i] = 0.0f;

    const float* adjb = adj + (size_t)(rb * 128) * NN;

    for (int jt = 0; jt < 32; jt++) {
        const int j0 = jh * 4096 + jt * 128;
        __syncthreads();  // prev tile's smem reads done (also orders f1s on jt=0)

        // ---- stage H tile: sHT[n][k] <- g_hT[n][j0+k], 256 rows x 128 k ----
        {
            const __half* hsrc = g_hT + j0;
#pragma unroll
            for (int i = 0; i < 8; i++) {
                int v = tid + i * 512;       // uint4 slot 0..4095 (16 per n-row)
                int n = v >> 4;
                int c = (v & 15) << 3;       // half offset within row
                *(uint4*)&sHT[n * SPH_STRIDE + c] =
                    *(const uint4*)(hsrc + (size_t)n * NN + c);
            }
        }

        // ---- P tile (fp16, shifted) + per-lane partial row sums ----
        // Warp w, iter i covers row r = w + 16*i (lane -> cols 4l..4l+3).
        float4 f2v = __ldg((const float4*)(g_f2 + j0 + 4 * lane));
#pragma unroll
        for (int i = 0; i < 8; i++) {
            int r = w + 16 * i;
            float f1v = f1s[r];
            float zc = f1v + m2;
            float c = fmaxf(zc, 0.01f * zc);         // row shift (same both halves)
            float4 av = __ldg((const float4*)(adjb + (size_t)r * NN + j0 + 4 * lane));
            float z0 = f1v + f2v.x, z1 = f1v + f2v.y;
            float z2 = f1v + f2v.z, z3 = f1v + f2v.w;
            float p0 = av.x * fexp(fmaxf(z0, 0.01f * z0) - c);
            float p1 = av.y * fexp(fmaxf(z1, 0.01f * z1) - c);
            float p2 = av.z * fexp(fmaxf(z2, 0.01f * z2) - c);
            float p3 = av.w * fexp(fmaxf(z3, 0.01f * z3) - c);
            __half2 h01 = __floats2half2_rn(p0, p1);
            __half2 h23 = __floats2half2_rn(p2, p3);
            union { __half2 h2[2]; uint2 u; } pk;
            pk.h2[0] = h01; pk.h2[1] = h23;
            *(uint2*)&sP[r * SPH_STRIDE + 4 * lane] = pk.u;
            // accumulate the fp16-ROUNDED values so l matches the numerator
            float2 q01 = __half22float2(h01);
            float2 q23 = __half22float2(h23);
            lacc[i] += (q01.x + q01.y) + (q23.x + q23.y);
        }
        __syncthreads();

        // ---- mma: acc += P[128x128] @ H[128x256] (fp16 in, fp32 acc) ----
#pragma unroll
        for (int kc = 0; kc < 8; kc++) {
            unsigned a[2][4];
#pragma unroll
            for (int mt = 0; mt < 2; mt++) {
                const __half* base =
                    &sP[(wm * 32 + mt * 16 + g) * SPH_STRIDE + kc * 16 + 2 * tq];
                a[mt][0] = *(const unsigned*)(base);                    // [g][2tq]
                a[mt][1] = *(const unsigned*)(base + 8 * SPH_STRIDE);   // [g+8][2tq]
                a[mt][2] = *(const unsigned*)(base + 8);                // [g][2tq+8]
                a[mt][3] = *(const unsigned*)(base + 8 * SPH_STRIDE + 8);
            }
#pragma unroll
            for (int nb = 0; nb < 8; nb++) {
                const __half* bb =
                    &sHT[(wn * 64 + nb * 8 + g) * SPH_STRIDE + kc * 16 + 2 * tq];
                unsigned b0 = *(const unsigned*)(bb);        // {H[2tq][n],H[2tq+1][n]}
                unsigned b1 = *(const unsigned*)(bb + 8);    // {H[2tq+8][n],H[2tq+9][n]}
#pragma unroll
                for (int mt = 0; mt < 2; mt++) mma_f16(acc[mt][nb], a[mt], b0, b1);
            }
        }
    }

    // ---- final row-sum reduce (hoisted out of tile loop) + store partial l ----
#pragma unroll
    for (int i = 0; i < 8; i++) {
        float s = lacc[i];
#pragma unroll
        for (int off = 16; off >= 1; off >>= 1)
            s += __shfl_xor_sync(0xffffffffu, s, off);
        if (lane == 0) g_l[jh * NN + rb * 128 + w + 16 * i] = s;
    }

    // ---- epilogue: partial O (stays L2-resident for k_out) ----
    float* Op = g_O + (size_t)jh * NN * DOUT;
#pragma unroll
    for (int mt = 0; mt < 2; mt++) {
        int row0 = rb * 128 + wm * 32 + mt * 16 + g;
#pragma unroll
        for (int nb = 0; nb < 8; nb++) {
            int col = wn * 64 + nb * 8 + tq * 2;
            *(float2*)&Op[(size_t)row0 * DOUT + col] =
                make_float2(acc[mt][nb][0], acc[mt][nb][1]);
            *(float2*)&Op[(size_t)(row0 + 8) * DOUT + col] =
                make_float2(acc[mt][nb][2], acc[mt][nb][3]);
        }
    }
}

// ---------------- kernel 4: combine halves, divide, elu ----------------
__global__ __launch_bounds__(256) void k_out(float* __restrict__ out) {
    int idx = blockIdx.x * 256 + threadIdx.x;   // 0 .. 2M-1
    int row = idx >> 8;
    float linv = 1.0f / (g_l[row] + g_l[NN + row]);
    float o = (g_O[idx] + g_O[NN * DOUT + idx]) * linv;
    out[idx] = (o > 0.0f) ? o : expm1f(o);
}

// ---------------- launch ----------------
extern "C" void kernel_launch(void* const* d_in, const int* in_sizes, int n_in,
                              void* d_out, int out_size) {
    const float* x   = (const float*)d_in[0];   // [8192, 512]
    const float* adj = (const float*)d_in[1];   // [8192, 8192]
    const float* W   = (const float*)d_in[2];   // [256, 512]
    const float* a1  = (const float*)d_in[3];   // [256]
    const float* a2  = (const float*)d_in[4];   // [256]
    float* out = (float*)d_out;                 // [8192, 256]

    (void)in_sizes; (void)n_in; (void)out_size;
    cudaFuncSetAttribute(k_attn, cudaFuncAttributeMaxDynamicSharedMemorySize,
                         SMEM_BYTES);

    k_gemm_h<<<dim3(2, 64), 256>>>(x, W);
    k_f1f2<<<NN / 8, 256>>>(a1, a2);
    k_max<<<1, 1024>>>();
    k_attn<<<dim3(2, 64), 512, SMEM_BYTES>>>(adj);
    k_out<<<(NN * DOUT) / 256, 256>>>(out);
}

// round 10
// speedup vs baseline: 2.0164x; 1.4308x over previous
#include <cuda_runtime.h>
#include <cuda_fp16.h>
#include <math.h>
#include <stdint.h>

#define NN 8192
#define DIN 512
#define DOUT 256

// ---------------- scratch (static device memory; no allocation) ----------------
__device__ __half g_hT[DOUT * NN];          // h transposed [n][j], fp16 (MMA B operand)
__device__ float g_b1[DIN];                 // W^T a1
__device__ float g_b2[DIN];                 // W^T a2
__device__ float g_f1[NN];
__device__ float g_f2[NN];
__device__ float g_m2;                      // global max of f2
__device__ float g_O[2 * NN * DOUT];        // partial O per j-half (16 MB)
__device__ float g_l[2 * NN];               // partial softmax denominators

// ---------------- helpers ----------------
// Fast exp via FMA-only range reduction + deg-4 poly + exponent splice.
// Input is (lrelu(z) - c) <= 0, > -40; rel err ~4e-5. No MUFU.
__device__ __forceinline__ float fexp(float x) {
    float j = fmaf(x, 1.4426950408889634f, 12582912.0f); // magic 1.5*2^23
    float n = j - 12582912.0f;                            // round(x*log2e)
    float f = fmaf(n, -0.693359375f, x);                  // Cody-Waite hi
    f = fmaf(n, 2.1219444e-4f, f);                        // Cody-Waite lo
    float r = fmaf(f, 0.041666668f, 0.16666667f);
    r = fmaf(r, f, 0.5f);
    r = fmaf(r, f, 1.0f);
    r = fmaf(r, f, 1.0f);                                 // e^f
    int sc = __float_as_int(j) << 23;                     // == n << 23
    return __int_as_float(__float_as_int(r) + sc);        // e^f * 2^n
}

// fp16 mma m16n8k16: A 4 regs (8 f16), B 2 regs (4 f16), C/D 4 f32.
__device__ __forceinline__ void mma_f16(float* d, const unsigned* a,
                                        unsigned b0, unsigned b1) {
    asm volatile(
        "mma.sync.aligned.m16n8k16.row.col.f32.f16.f16.f32 "
        "{%0,%1,%2,%3}, {%4,%5,%6,%7}, {%8,%9}, {%0,%1,%2,%3};\n"
        : "+f"(d[0]), "+f"(d[1]), "+f"(d[2]), "+f"(d[3])
        : "r"(a[0]), "r"(a[1]), "r"(a[2]), "r"(a[3]), "r"(b0), "r"(b1));
}

__device__ __forceinline__ void cp_async16(uint32_t saddr, const void* gptr) {
    asm volatile("cp.async.cg.shared.global [%0], [%1], 16;\n"
                 :: "r"(saddr), "l"(gptr));
}
#define CP_COMMIT() asm volatile("cp.async.commit_group;\n" ::: "memory")
#define CP_WAIT0()  asm volatile("cp.async.wait_group 0;\n" ::: "memory")

// ---------------- kernel 1: hT = W @ x^T via fp16 mma ----------------
// grid (2, 64): blockIdx.x = 128-row block of DOUT (n), blockIdx.y = 128-col block of N (j).
// A = W[n][k] row-major, B = x^T[k][j] (x row-major gives k-contiguous). fp32 accum.
__global__ __launch_bounds__(512) void k_h(const float* __restrict__ x,
                                           const float* __restrict__ W) {
    __shared__ __half sW[128 * 72];          // [n][k] chunk, stride 72
    __shared__ __half sX[128 * 72];          // [j][k] chunk, stride 72
    const int tid = threadIdx.x;
    const int lane = tid & 31, w = tid >> 5;
    const int wm = w >> 2, wn = w & 3;       // 4 (n) x 4 (j) warp grid
    const int g = lane >> 2, tq = lane & 3;
    const int n0 = blockIdx.x * 128, j0 = blockIdx.y * 128;

    float acc[2][4][4];
#pragma unroll
    for (int mt = 0; mt < 2; mt++)
#pragma unroll
        for (int jb = 0; jb < 4; jb++)
#pragma unroll
            for (int q = 0; q < 4; q++) acc[mt][jb][q] = 0.0f;

    for (int kc = 0; kc < 8; kc++) {
        const int k0 = kc * 64;
        __syncthreads();                     // prev chunk's reads done
#pragma unroll
        for (int q = 0; q < 4; q++) {
            int v = tid + q * 512;           // float4 slot 0..2047
            int r = v >> 4, c = (v & 15) << 2;
            float4 wv = __ldg((const float4*)(W + (size_t)(n0 + r) * DIN + k0 + c));
            float4 xv = __ldg((const float4*)(x + (size_t)(j0 + r) * DIN + k0 + c));
            __half2 wh[2] = {__floats2half2_rn(wv.x, wv.y), __floats2half2_rn(wv.z, wv.w)};
            __half2 xh[2] = {__floats2half2_rn(xv.x, xv.y), __floats2half2_rn(xv.z, xv.w)};
            *(uint2*)&sW[r * 72 + c] = *(const uint2*)wh;
            *(uint2*)&sX[r * 72 + c] = *(const uint2*)xh;
        }
        __syncthreads();
#pragma unroll
        for (int ks = 0; ks < 4; ks++) {
            unsigned a[2][4];
#pragma unroll
            for (int mt = 0; mt < 2; mt++) {
                const __half* base = &sW[(wm * 32 + mt * 16 + g) * 72 + ks * 16 + 2 * tq];
                a[mt][0] = *(const unsigned*)(base);
                a[mt][1] = *(const unsigned*)(base + 8 * 72);
                a[mt][2] = *(const unsigned*)(base + 8);
                a[mt][3] = *(const unsigned*)(base + 8 * 72 + 8);
            }
#pragma unroll
            for (int jb = 0; jb < 4; jb++) {
                const __half* bb = &sX[(wn * 32 + jb * 8 + g) * 72 + ks * 16 + 2 * tq];
                unsigned b0 = *(const unsigned*)(bb);
                unsigned b1 = *(const unsigned*)(bb + 8);
#pragma unroll
                for (int mt = 0; mt < 2; mt++) mma_f16(acc[mt][jb], a[mt], b0, b1);
            }
        }
    }
    // store hT fp16: D rows = n (g, g+8), cols = j (2tq, 2tq+1)
#pragma unroll
    for (int mt = 0; mt < 2; mt++) {
        int n = n0 + wm * 32 + mt * 16 + g;
#pragma unroll
        for (int jb = 0; jb < 4; jb++) {
            int j = j0 + wn * 32 + jb * 8 + 2 * tq;
            *(__half2*)&g_hT[(size_t)n * NN + j] =
                __floats2half2_rn(acc[mt][jb][0], acc[mt][jb][1]);
            *(__half2*)&g_hT[(size_t)(n + 8) * NN + j] =
                __floats2half2_rn(acc[mt][jb][2], acc[mt][jb][3]);
        }
    }
}

// ---------------- kernel 2a: b1 = W^T a1, b2 = W^T a2 (fp32-exact path) -------
__global__ __launch_bounds__(512) void k_vec(const float* __restrict__ W,
                                             const float* __restrict__ a1,
                                             const float* __restrict__ a2) {
    __shared__ float as[DOUT];
    const float* a = blockIdx.x ? a2 : a1;
    float* out = blockIdx.x ? g_b2 : g_b1;
    int tid = threadIdx.x;
    if (tid < DOUT) as[tid] = a[tid];
    __syncthreads();
    float s = 0.0f;
#pragma unroll 16
    for (int i = 0; i < DOUT; i++)
        s = fmaf(__ldg(W + (size_t)i * DIN + tid), as[i], s);
    out[tid] = s;
}

// ---------------- kernel 2b: f1 = x@b1, f2 = x@b2 (fp32) ----------------
__global__ __launch_bounds__(256) void k_f12(const float* __restrict__ x) {
    __shared__ float b1s[DIN], b2s[DIN];
    int tid = threadIdx.x;
    b1s[tid] = g_b1[tid]; b1s[tid + 256] = g_b1[tid + 256];
    b2s[tid] = g_b2[tid]; b2s[tid + 256] = g_b2[tid + 256];
    __syncthreads();
    int w = tid >> 5, lane = tid & 31;
    int row = blockIdx.x * 8 + w;
    const float* xr = x + (size_t)row * DIN;
    float s1 = 0.0f, s2 = 0.0f;
#pragma unroll
    for (int q = 0; q < 4; q++) {
        float4 xv = __ldg((const float4*)(xr + q * 128 + lane * 4));
        int c = q * 128 + lane * 4;
        s1 = fmaf(xv.x, b1s[c], fmaf(xv.y, b1s[c + 1],
             fmaf(xv.z, b1s[c + 2], fmaf(xv.w, b1s[c + 3], s1))));
        s2 = fmaf(xv.x, b2s[c], fmaf(xv.y, b2s[c + 1],
             fmaf(xv.z, b2s[c + 2], fmaf(xv.w, b2s[c + 3], s2))));
    }
#pragma unroll
    for (int off = 16; off >= 1; off >>= 1) {
        s1 += __shfl_xor_sync(0xffffffffu, s1, off);
        s2 += __shfl_xor_sync(0xffffffffu, s2, off);
    }
    if (lane == 0) { g_f1[row] = s1; g_f2[row] = s2; }
}

// ---------------- kernel 2c: global max of f2 (order-independent) -------------
__global__ __launch_bounds__(1024) void k_max() {
    __shared__ float red[32];
    int tid = threadIdx.x;
    float m = -1e30f;
#pragma unroll
    for (int i = 0; i < 8; i++) m = fmaxf(m, g_f2[tid + i * 1024]);
#pragma unroll
    for (int off = 16; off >= 1; off >>= 1)
        m = fmaxf(m, __shfl_xor_sync(0xffffffffu, m, off));
    if ((tid & 31) == 0) red[tid >> 5] = m;
    __syncthreads();
    if (tid < 32) {
        m = red[tid];
#pragma unroll
        for (int off = 16; off >= 1; off >>= 1)
            m = fmaxf(m, __shfl_xor_sync(0xffffffffu, m, off));
        if (tid == 0) g_m2 = m;
    }
}

// ---------------- kernel 3: fused softmax-numerator @ h, PIPELINED ------------
// grid (2, 64). 512 threads, 16 warps (4x4). Double-buffered sP/sHT, ONE barrier
// per tile: body = [write bufs(t); sync; MMA(t)]. Warp drift overlaps one warp's
// MMA with another's P-phase. Safety: writer of t+1 passed sync(t), which all
// warps reach only after finishing MMA(t-1) on that same buffer.
#define SPH 136
#define SP_HALFS   (128 * SPH)                  // 17408 halves per buf
#define SHT_HALFS  (256 * SPH)                  // 34816 halves per buf
#define F1_BYTEOFF (4 * SP_HALFS + 4 * SHT_HALFS) // 2 bufs each, bytes = halves*2
#define SMEM_BYTES (F1_BYTEOFF + 512)           // 209408
__global__ __launch_bounds__(512, 1) void k_attn(const float* __restrict__ adj) {
    extern __shared__ __align__(16) __half smh[];
    float* f1s = (float*)((char*)smh + F1_BYTEOFF);

    const int tid = threadIdx.x;
    const int jh = blockIdx.x, rb = blockIdx.y;
    const int lane = tid & 31, w = tid >> 5;
    const int wm = w >> 2, wn = w & 3;
    const int g = lane >> 2, tq = lane & 3;

    if (tid < 128) f1s[tid] = g_f1[rb * 128 + tid];
    const float m2 = g_m2;
    __syncthreads();                         // f1s visible before first P-phase

    float acc[2][8][4];
#pragma unroll
    for (int mt = 0; mt < 2; mt++)
#pragma unroll
        for (int nb = 0; nb < 8; nb++)
#pragma unroll
            for (int q = 0; q < 4; q++) acc[mt][nb][q] = 0.0f;

    float lacc[8];
#pragma unroll
    for (int i = 0; i < 8; i++) lacc[i] = 0.0f;

    const float* adjb = adj + (size_t)(rb * 128) * NN;
    const uint32_t smbase = (uint32_t)__cvta_generic_to_shared(smh);

    for (int jt = 0; jt < 32; jt++) {
        const int b = jt & 1;
        const int j0 = jh * 4096 + jt * 128;
        __half* sP  = smh + b * SP_HALFS;
        __half* sHT = smh + 2 * SP_HALFS + b * SHT_HALFS;
        const uint32_t sht_b = smbase + (2 * SP_HALFS + b * SHT_HALFS) * 2;

        // ---- stage H tile via cp.async (no register round-trip) ----
        {
            const __half* hsrc = g_hT + j0;
#pragma unroll
            for (int i = 0; i < 8; i++) {
                int v = tid + i * 512;       // 16B chunk 0..4095
                int n = v >> 4;
                int c = (v & 15) << 3;       // half offset in row
                cp_async16(sht_b + (n * SPH + c) * 2, hsrc + (size_t)n * NN + c);
            }
            CP_COMMIT();
        }

        // ---- P tile: batch all adj loads (MLP=8), then compute ----
        float4 f2v = __ldg((const float4*)(g_f2 + j0 + 4 * lane));
        float4 av[8];
#pragma unroll
        for (int i = 0; i < 8; i++)
            av[i] = __ldg((const float4*)(adjb + (size_t)(w + 16 * i) * NN + j0 + 4 * lane));
#pragma unroll
        for (int i = 0; i < 8; i++) {
            int r = w + 16 * i;
            float f1v = f1s[r];
            float zc = f1v + m2;
            float c = fmaxf(zc, 0.01f * zc);       // row shift (same both halves)
            float z0 = f1v + f2v.x, z1 = f1v + f2v.y;
            float z2 = f1v + f2v.z, z3 = f1v + f2v.w;
            float p0 = av[i].x * fexp(fmaxf(z0, 0.01f * z0) - c);
            float p1 = av[i].y * fexp(fmaxf(z1, 0.01f * z1) - c);
            float p2 = av[i].z * fexp(fmaxf(z2, 0.01f * z2) - c);
            float p3 = av[i].w * fexp(fmaxf(z3, 0.01f * z3) - c);
            __half2 h01 = __floats2half2_rn(p0, p1);
            __half2 h23 = __floats2half2_rn(p2, p3);
            union { __half2 h2[2]; uint2 u; } pk;
            pk.h2[0] = h01; pk.h2[1] = h23;
            *(uint2*)&sP[r * SPH + 4 * lane] = pk.u;
            float2 q01 = __half22float2(h01);      // sum fp16-ROUNDED values
            float2 q23 = __half22float2(h23);
            lacc[i] += (q01.x + q01.y) + (q23.x + q23.y);
        }
        CP_WAIT0();
        __syncthreads();                     // bufs(t) ready for everyone

        // ---- mma: acc += P[128x128] @ H[128x256] ----
#pragma unroll
        for (int kc = 0; kc < 8; kc++) {
            unsigned a[2][4];
#pragma unroll
            for (int mt = 0; mt < 2; mt++) {
                const __half* base = &sP[(wm * 32 + mt * 16 + g) * SPH + kc * 16 + 2 * tq];
                a[mt][0] = *(const unsigned*)(base);
                a[mt][1] = *(const unsigned*)(base + 8 * SPH);
                a[mt][2] = *(const unsigned*)(base + 8);
                a[mt][3] = *(const unsigned*)(base + 8 * SPH + 8);
            }
#pragma unroll
            for (int nb = 0; nb < 8; nb++) {
                const __half* bb = &sHT[(wn * 64 + nb * 8 + g) * SPH + kc * 16 + 2 * tq];
                unsigned b0 = *(const unsigned*)(bb);
                unsigned b1 = *(const unsigned*)(bb + 8);
#pragma unroll
                for (int mt = 0; mt < 2; mt++) mma_f16(acc[mt][nb], a[mt], b0, b1);
            }
        }
    }

    // ---- final row-sum reduce + store partial l ----
#pragma unroll
    for (int i = 0; i < 8; i++) {
        float s = lacc[i];
#pragma unroll
        for (int off = 16; off >= 1; off >>= 1)
            s += __shfl_xor_sync(0xffffffffu, s, off);
        if (lane == 0) g_l[jh * NN + rb * 128 + w + 16 * i] = s;
    }

    // ---- epilogue: partial O ----
    float* Op = g_O + (size_t)jh * NN * DOUT;
#pragma unroll
    for (int mt = 0; mt < 2; mt++) {
        int row0 = rb * 128 + wm * 32 + mt * 16 + g;
#pragma unroll
        for (int nb = 0; nb < 8; nb++) {
            int col = wn * 64 + nb * 8 + tq * 2;
            *(float2*)&Op[(size_t)row0 * DOUT + col] =
                make_float2(acc[mt][nb][0], acc[mt][nb][1]);
            *(float2*)&Op[(size_t)(row0 + 8) * DOUT + col] =
                make_float2(acc[mt][nb][2], acc[mt][nb][3]);
        }
    }
}

// ---------------- kernel 4: combine halves, divide, elu ----------------
__global__ __launch_bounds__(256) void k_out(float* __restrict__ out) {
    int idx = blockIdx.x * 256 + threadIdx.x;
    int row = idx >> 8;
    float linv = 1.0f / (g_l[row] + g_l[NN + row]);
    float o = (g_O[idx] + g_O[NN * DOUT + idx]) * linv;
    out[idx] = (o > 0.0f) ? o : expm1f(o);
}

// ---------------- launch ----------------
extern "C" void kernel_launch(void* const* d_in, const int* in_sizes, int n_in,
                              void* d_out, int out_size) {
    const float* x   = (const float*)d_in[0];   // [8192, 512]
    const float* adj = (const float*)d_in[1];   // [8192, 8192]
    const float* W   = (const float*)d_in[2];   // [256, 512]
    const float* a1  = (const float*)d_in[3];   // [256]
    const float* a2  = (const float*)d_in[4];   // [256]
    float* out = (float*)d_out;                 // [8192, 256]

    (void)in_sizes; (void)n_in; (void)out_size;
    cudaFuncSetAttribute(k_attn, cudaFuncAttributeMaxDynamicSharedMemorySize,
                         SMEM_BYTES);

    k_h<<<dim3(2, 64), 512>>>(x, W);
    k_vec<<<2, 512>>>(W, a1, a2);
    k_f12<<<NN / 8, 256>>>(x);
    k_max<<<1, 1024>>>();
    k_attn<<<dim3(2, 64), 512, SMEM_BYTES>>>(adj);
    k_out<<<(NN * DOUT) / 256, 256>>>(out);
}

// round 12
// speedup vs baseline: 2.1399x; 1.0613x over previous
#include <cuda_runtime.h>
#include <cuda_fp16.h>
#include <math.h>
#include <stdint.h>

#define NN 8192
#define DIN 512
#define DOUT 256

// ---------------- scratch (static device memory; no allocation) ----------------
__device__ __half g_xh[NN * DIN];           // x in fp16
__device__ __half g_wh[DOUT * DIN];         // W in fp16
__device__ __half g_hT[DOUT * NN];          // h transposed [n][j], fp16 (MMA B operand)
__device__ float g_b1[DIN];                 // W^T a1
__device__ float g_b2[DIN];                 // W^T a2
__device__ float g_f1[NN];
__device__ float g_f2[NN];
__device__ unsigned g_m2key;                // monotone-key max of f2
__device__ float g_O[2 * NN * DOUT];        // partial O per j-half (16 MB)
__device__ float g_l[2 * NN];               // partial softmax denominators

// ---------------- helpers ----------------
// Fast exp via FMA-only range reduction + deg-4 poly + exponent splice.
// Input is (lrelu(z) - c) <= 0, > -40; rel err ~4e-5. No MUFU.
__device__ __forceinline__ float fexp(float x) {
    float j = fmaf(x, 1.4426950408889634f, 12582912.0f);
    float n = j - 12582912.0f;
    float f = fmaf(n, -0.693359375f, x);
    f = fmaf(n, 2.1219444e-4f, f);
    float r = fmaf(f, 0.041666668f, 0.16666667f);
    r = fmaf(r, f, 0.5f);
    r = fmaf(r, f, 1.0f);
    r = fmaf(r, f, 1.0f);
    int sc = __float_as_int(j) << 23;
    return __int_as_float(__float_as_int(r) + sc);
}

__device__ __forceinline__ void mma_f16(float* d, const unsigned* a,
                                        unsigned b0, unsigned b1) {
    asm volatile(
        "mma.sync.aligned.m16n8k16.row.col.f32.f16.f16.f32 "
        "{%0,%1,%2,%3}, {%4,%5,%6,%7}, {%8,%9}, {%0,%1,%2,%3};\n"
        : "+f"(d[0]), "+f"(d[1]), "+f"(d[2]), "+f"(d[3])
        : "r"(a[0]), "r"(a[1]), "r"(a[2]), "r"(a[3]), "r"(b0), "r"(b1));
}

__device__ __forceinline__ void ldsm_x4(unsigned& r0, unsigned& r1,
                                        unsigned& r2, unsigned& r3, uint32_t addr) {
    asm volatile("ldmatrix.sync.aligned.m8n8.x4.shared.b16 {%0,%1,%2,%3}, [%4];"
                 : "=r"(r0), "=r"(r1), "=r"(r2), "=r"(r3) : "r"(addr));
}

__device__ __forceinline__ void cp_async16(uint32_t saddr, const void* gptr) {
    asm volatile("cp.async.cg.shared.global [%0], [%1], 16;\n"
                 :: "r"(saddr), "l"(gptr));
}
#define CP_COMMIT() asm volatile("cp.async.commit_group;\n" ::: "memory")
#define CP_WAIT(N)  asm volatile("cp.async.wait_group %0;\n" :: "n"(N) : "memory")

// monotone key: unsigned order == float order
__device__ __forceinline__ unsigned f2key(float x) {
    unsigned u = __float_as_uint(x);
    return ((int)u >= 0) ? (u | 0x80000000u) : ~u;
}

// ---------------- kernel 0: convert x, W to fp16 ----------------
__global__ __launch_bounds__(256) void k_cvt(const float* __restrict__ x,
                                             const float* __restrict__ W) {
    int b = blockIdx.x;
    const float* src;
    __half* dst;
    size_t v;
    if (b < 4096) { src = x; dst = g_xh; v = (size_t)b * 256 + threadIdx.x; }
    else          { src = W; dst = g_wh; v = (size_t)(b - 4096) * 256 + threadIdx.x; }
    float4 f = __ldg((const float4*)src + v);
    union { __half2 h[2]; uint2 u; } pk;
    pk.h[0] = __floats2half2_rn(f.x, f.y);
    pk.h[1] = __floats2half2_rn(f.z, f.w);
    *(uint2*)&dst[v * 4] = pk.u;
}

// ---------------- kernel 1: hT = W @ x^T via fp16 mma + cp.async pipeline -----
// grid (2, 64): blockIdx.x = 128-row block of DOUT (n), blockIdx.y = 128 j-cols.
// DYNAMIC smem (73,728 B > 48 KB static limit): sW[2][128*72], sX[2][128*72].
#define KH_S 72
#define KH_BUF (128 * KH_S)                  // halves per buffer
#define KH_SMEM_BYTES (4 * KH_BUF * 2)       // 73728
__global__ __launch_bounds__(512) void k_h() {
    extern __shared__ __align__(16) __half kh_sm[];
    __half* sW = kh_sm;                      // 2 bufs of KH_BUF
    __half* sX = kh_sm + 2 * KH_BUF;         // 2 bufs of KH_BUF
    const int tid = threadIdx.x;
    const int lane = tid & 31, w = tid >> 5;
    const int wm = w >> 2, wn = w & 3;       // 4 (n) x 4 (j) warp grid
    const int g = lane >> 2, tq = lane & 3;
    const int n0 = blockIdx.x * 128, j0 = blockIdx.y * 128;
    const uint32_t swb = (uint32_t)__cvta_generic_to_shared(sW);
    const uint32_t sxb = (uint32_t)__cvta_generic_to_shared(sX);

    float acc[2][4][4];
#pragma unroll
    for (int mt = 0; mt < 2; mt++)
#pragma unroll
        for (int jb = 0; jb < 4; jb++)
#pragma unroll
            for (int q = 0; q < 4; q++) acc[mt][jb][q] = 0.0f;

    // ldmatrix base offsets (halves)
    const int aoff = (wm * 32 + (lane & 15)) * KH_S + (lane >> 4) * 8;
    const int boff = (wn * 32 + (lane & 7) + ((lane & 16) ? 8 : 0)) * KH_S +
                     ((lane >> 3) & 1) * 8;

    // stage chunk c into buffer c&1 (2 cp per array per thread)
    auto issue = [&](int c) {
        int k0 = c * 64;
        int bsel = (c & 1) * KH_BUF;
#pragma unroll
        for (int q = 0; q < 2; q++) {
            int v = tid + q * 512;           // 0..1023
            int r = v >> 3, ck = (v & 7) << 3;
            cp_async16(swb + (bsel + r * KH_S + ck) * 2,
                       g_wh + (size_t)(n0 + r) * DIN + k0 + ck);
            cp_async16(sxb + (bsel + r * KH_S + ck) * 2,
                       g_xh + (size_t)(j0 + r) * DIN + k0 + ck);
        }
    };

    issue(0); CP_COMMIT();
    for (int c = 0; c < 8; c++) {
        __syncthreads();                     // mma(c-1) done -> buf (c+1)&1 free
        if (c < 7) { issue(c + 1); CP_COMMIT(); }
        if (c < 7) { CP_WAIT(1); } else { CP_WAIT(0); }
        __syncthreads();                     // chunk c visible
        const uint32_t aB = swb + ((c & 1) * KH_BUF + aoff) * 2;
        const uint32_t bB = sxb + ((c & 1) * KH_BUF + boff) * 2;
#pragma unroll
        for (int ks = 0; ks < 4; ks++) {
            unsigned A0[4], A1[4];
            ldsm_x4(A0[0], A0[1], A0[2], A0[3], aB + (ks * 16) * 2);
            ldsm_x4(A1[0], A1[1], A1[2], A1[3], aB + (16 * KH_S + ks * 16) * 2);
#pragma unroll
            for (int jp = 0; jp < 2; jp++) {
                unsigned B[4];
                ldsm_x4(B[0], B[1], B[2], B[3], bB + (jp * 16 * KH_S + ks * 16) * 2);
                mma_f16(acc[0][2 * jp], A0, B[0], B[1]);
                mma_f16(acc[0][2 * jp + 1], A0, B[2], B[3]);
                mma_f16(acc[1][2 * jp], A1, B[0], B[1]);
                mma_f16(acc[1][2 * jp + 1], A1, B[2], B[3]);
            }
        }
    }
    // store hT fp16: rows n (g, g+8), cols j (2tq, 2tq+1)
#pragma unroll
    for (int mt = 0; mt < 2; mt++) {
        int n = n0 + wm * 32 + mt * 16 + g;
#pragma unroll
        for (int jb = 0; jb < 4; jb++) {
            int j = j0 + wn * 32 + jb * 8 + 2 * tq;
            *(__half2*)&g_hT[(size_t)n * NN + j] =
                __floats2half2_rn(acc[mt][jb][0], acc[mt][jb][1]);
            *(__half2*)&g_hT[(size_t)(n + 8) * NN + j] =
                __floats2half2_rn(acc[mt][jb][2], acc[mt][jb][3]);
        }
    }
}

// ---------------- kernel 2a: b1 = W^T a1, b2 = W^T a2; init m2key -------------
__global__ __launch_bounds__(512) void k_vec(const float* __restrict__ W,
                                             const float* __restrict__ a1,
                                             const float* __restrict__ a2) {
    __shared__ float as[DOUT];
    const float* a = blockIdx.x ? a2 : a1;
    float* out = blockIdx.x ? g_b2 : g_b1;
    int tid = threadIdx.x;
    if (blockIdx.x == 0 && tid == 0) g_m2key = 0u;   // reset (graph replays)
    if (tid < DOUT) as[tid] = a[tid];
    __syncthreads();
    float s = 0.0f;
#pragma unroll 16
    for (int i = 0; i < DOUT; i++)
        s = fmaf(__ldg(W + (size_t)i * DIN + tid), as[i], s);
    out[tid] = s;
}

// ---------------- kernel 2b: f1 = x@b1, f2 = x@b2 (fp32) + global max f2 ------
__global__ __launch_bounds__(256) void k_f12(const float* __restrict__ x) {
    __shared__ float b1s[DIN], b2s[DIN];
    __shared__ float mx[8];
    int tid = threadIdx.x;
    b1s[tid] = g_b1[tid]; b1s[tid + 256] = g_b1[tid + 256];
    b2s[tid] = g_b2[tid]; b2s[tid + 256] = g_b2[tid + 256];
    __syncthreads();
    int w = tid >> 5, lane = tid & 31;
    int row = blockIdx.x * 8 + w;
    const float* xr = x + (size_t)row * DIN;
    float s1 = 0.0f, s2 = 0.0f;
#pragma unroll
    for (int q = 0; q < 4; q++) {
        float4 xv = __ldg((const float4*)(xr + q * 128 + lane * 4));
        int c = q * 128 + lane * 4;
        s1 = fmaf(xv.x, b1s[c], fmaf(xv.y, b1s[c + 1],
             fmaf(xv.z, b1s[c + 2], fmaf(xv.w, b1s[c + 3], s1))));
        s2 = fmaf(xv.x, b2s[c], fmaf(xv.y, b2s[c + 1],
             fmaf(xv.z, b2s[c + 2], fmaf(xv.w, b2s[c + 3], s2))));
    }
#pragma unroll
    for (int off = 16; off >= 1; off >>= 1) {
        s1 += __shfl_xor_sync(0xffffffffu, s1, off);
        s2 += __shfl_xor_sync(0xffffffffu, s2, off);
    }
    if (lane == 0) { g_f1[row] = s1; g_f2[row] = s2; mx[w] = s2; }
    __syncthreads();
    if (tid == 0) {
        float m = mx[0];
#pragma unroll
        for (int i = 1; i < 8; i++) m = fmaxf(m, mx[i]);
        atomicMax(&g_m2key, f2key(m));       // order-independent -> deterministic
    }
}

// ---------------- kernel 3: fused softmax-numerator @ h, pipelined + ldmatrix -
// grid (2, 64). 512 threads, 16 warps (4x4). Double-buffered sP/sHT, one barrier
// per tile; warp drift overlaps P-phase with MMA across warps.
#define SPH 136
#define SP_HALFS   (128 * SPH)
#define SHT_HALFS  (256 * SPH)
#define F1_BYTEOFF (4 * SP_HALFS + 4 * SHT_HALFS)
#define SMEM_BYTES (F1_BYTEOFF + 512)           // 209408
__global__ __launch_bounds__(512, 1) void k_attn(const float* __restrict__ adj) {
    extern __shared__ __align__(16) __half smh[];
    float* f1s = (float*)((char*)smh + F1_BYTEOFF);

    const int tid = threadIdx.x;
    const int jh = blockIdx.x, rb = blockIdx.y;
    const int lane = tid & 31, w = tid >> 5;
    const int wm = w >> 2, wn = w & 3;
    const int g = lane >> 2, tq = lane & 3;

    if (tid < 128) f1s[tid] = g_f1[rb * 128 + tid];
    unsigned mk = g_m2key;
    const float m2 = (mk & 0x80000000u) ? __uint_as_float(mk & 0x7FFFFFFFu)
                                        : __uint_as_float(~mk);
    __syncthreads();

    float acc[2][8][4];
#pragma unroll
    for (int mt = 0; mt < 2; mt++)
#pragma unroll
        for (int nb = 0; nb < 8; nb++)
#pragma unroll
            for (int q = 0; q < 4; q++) acc[mt][nb][q] = 0.0f;

    float lacc[8];
#pragma unroll
    for (int i = 0; i < 8; i++) lacc[i] = 0.0f;

    const float* adjb = adj + (size_t)(rb * 128) * NN;
    const uint32_t smbase = (uint32_t)__cvta_generic_to_shared(smh);

    // ldmatrix per-lane base offsets (halves, buffer-relative)
    const int aoff = (wm * 32 + (lane & 15)) * SPH + (lane >> 4) * 8;
    const int boff = (wn * 64 + (lane & 7) + ((lane & 16) ? 8 : 0)) * SPH +
                     ((lane >> 3) & 1) * 8;

    for (int jt = 0; jt < 32; jt++) {
        const int b = jt & 1;
        const int j0 = jh * 4096 + jt * 128;
        __half* sP = smh + b * SP_HALFS;
        const uint32_t sht_b = smbase + (2 * SP_HALFS + b * SHT_HALFS) * 2;

        // ---- stage H tile via cp.async ----
        {
            const __half* hsrc = g_hT + j0;
#pragma unroll
            for (int i = 0; i < 8; i++) {
                int v = tid + i * 512;
                int n = v >> 4;
                int c = (v & 15) << 3;
                cp_async16(sht_b + (n * SPH + c) * 2, hsrc + (size_t)n * NN + c);
            }
            CP_COMMIT();
        }

        // ---- P tile: batched adj loads (MLP=8), then compute ----
        float4 f2v = __ldg((const float4*)(g_f2 + j0 + 4 * lane));
        float4 av[8];
#pragma unroll
        for (int i = 0; i < 8; i++)
            av[i] = __ldg((const float4*)(adjb + (size_t)(w + 16 * i) * NN + j0 + 4 * lane));
#pragma unroll
        for (int i = 0; i < 8; i++) {
            int r = w + 16 * i;
            float f1v = f1s[r];
            float zc = f1v + m2;
            float c = fmaxf(zc, 0.01f * zc);     // row shift (same both halves)
            float z0 = f1v + f2v.x, z1 = f1v + f2v.y;
            float z2 = f1v + f2v.z, z3 = f1v + f2v.w;
            float p0 = av[i].x * fexp(fmaxf(z0, 0.01f * z0) - c);
            float p1 = av[i].y * fexp(fmaxf(z1, 0.01f * z1) - c);
            float p2 = av[i].z * fexp(fmaxf(z2, 0.01f * z2) - c);
            float p3 = av[i].w * fexp(fmaxf(z3, 0.01f * z3) - c);
            __half2 h01 = __floats2half2_rn(p0, p1);
            __half2 h23 = __floats2half2_rn(p2, p3);
            union { __half2 h2[2]; uint2 u; } pk;
            pk.h2[0] = h01; pk.h2[1] = h23;
            *(uint2*)&sP[r * SPH + 4 * lane] = pk.u;
            float2 q01 = __half22float2(h01);    // sum fp16-ROUNDED values
            float2 q23 = __half22float2(h23);
            lacc[i] += (q01.x + q01.y) + (q23.x + q23.y);
        }
        CP_WAIT(0);
        __syncthreads();

        // ---- mma via ldmatrix.x4: acc += P[128x128] @ H[128x256] ----
        const uint32_t aB = smbase + (b * SP_HALFS + aoff) * 2;
        const uint32_t bB = smbase + (2 * SP_HALFS + b * SHT_HALFS + boff) * 2;
#pragma unroll
        for (int kc = 0; kc < 8; kc++) {
            unsigned A0[4], A1[4];
            ldsm_x4(A0[0], A0[1], A0[2], A0[3], aB + (kc * 16) * 2);
            ldsm_x4(A1[0], A1[1], A1[2], A1[3], aB + (16 * SPH + kc * 16) * 2);
#pragma unroll
            for (int np = 0; np < 4; np++) {
                unsigned B[4];
                ldsm_x4(B[0], B[1], B[2], B[3], bB + (np * 16 * SPH + kc * 16) * 2);
                mma_f16(acc[0][2 * np], A0, B[0], B[1]);
                mma_f16(acc[0][2 * np + 1], A0, B[2], B[3]);
                mma_f16(acc[1][2 * np], A1, B[0], B[1]);
                mma_f16(acc[1][2 * np + 1], A1, B[2], B[3]);
            }
        }
    }

    // ---- final row-sum reduce + store partial l ----
#pragma unroll
    for (int i = 0; i < 8; i++) {
        float s = lacc[i];
#pragma unroll
        for (int off = 16; off >= 1; off >>= 1)
            s += __shfl_xor_sync(0xffffffffu, s, off);
        if (lane == 0) g_l[jh * NN + rb * 128 + w + 16 * i] = s;
    }

    // ---- epilogue: partial O ----
    float* Op = g_O + (size_t)jh * NN * DOUT;
#pragma unroll
    for (int mt = 0; mt < 2; mt++) {
        int row0 = rb * 128 + wm * 32 + mt * 16 + g;
#pragma unroll
        for (int nb = 0; nb < 8; nb++) {
            int col = wn * 64 + nb * 8 + tq * 2;
            *(float2*)&Op[(size_t)row0 * DOUT + col] =
                make_float2(acc[mt][nb][0], acc[mt][nb][1]);
            *(float2*)&Op[(size_t)(row0 + 8) * DOUT + col] =
                make_float2(acc[mt][nb][2], acc[mt][nb][3]);
        }
    }
}

// ---------------- kernel 4: combine halves, divide, elu ----------------
__global__ __launch_bounds__(256) void k_out(float* __restrict__ out) {
    int idx = blockIdx.x * 256 + threadIdx.x;
    int row = idx >> 8;
    float linv = 1.0f / (g_l[row] + g_l[NN + row]);
    float o = (g_O[idx] + g_O[NN * DOUT + idx]) * linv;
    out[idx] = (o > 0.0f) ? o : expm1f(o);
}

// ---------------- launch ----------------
extern "C" void kernel_launch(void* const* d_in, const int* in_sizes, int n_in,
                              void* d_out, int out_size) {
    const float* x   = (const float*)d_in[0];   // [8192, 512]
    const float* adj = (const float*)d_in[1];   // [8192, 8192]
    const float* W   = (const float*)d_in[2];   // [256, 512]
    const float* a1  = (const float*)d_in[3];   // [256]
    const float* a2  = (const float*)d_in[4];   // [256]
    float* out = (float*)d_out;                 // [8192, 256]

    (void)in_sizes; (void)n_in; (void)out_size;
    cudaFuncSetAttribute(k_attn, cudaFuncAttributeMaxDynamicSharedMemorySize,
                         SMEM_BYTES);
    cudaFuncSetAttribute(k_h, cudaFuncAttributeMaxDynamicSharedMemorySize,
                         KH_SMEM_BYTES);

    k_cvt<<<4224, 256>>>(x, W);
    k_h<<<dim3(2, 64), 512, KH_SMEM_BYTES>>>();
    k_vec<<<2, 512>>>(W, a1, a2);
    k_f12<<<NN / 8, 256>>>(x);
    k_attn<<<dim3(2, 64), 512, SMEM_BYTES>>>(adj);
    k_out<<<(NN * DOUT) / 256, 256>>>(out);
}

// round 13
// speedup vs baseline: 2.1592x; 1.0090x over previous
#include <cuda_runtime.h>
#include <cuda_fp16.h>
#include <math.h>
#include <stdint.h>

#define NN 8192
#define DIN 512
#define DOUT 256

// ---------------- scratch (static device memory; no allocation) ----------------
__device__ __half g_xh[NN * DIN];           // x in fp16
__device__ __half g_wh[DOUT * DIN];         // W in fp16
__device__ __half g_hT[DOUT * NN];          // h transposed [n][j], fp16 (MMA B operand)
__device__ float g_b1[DIN];                 // W^T a1
__device__ float g_b2[DIN];                 // W^T a2
__device__ float g_f1[NN];
__device__ float g_f2[NN];
__device__ float g_u[NN];                   // exp(f2)
__device__ float g_v[NN];                   // exp(0.01*f2)
__device__ unsigned g_m2key;                // monotone-key max of f2
__device__ float g_O[2 * NN * DOUT];        // partial O per j-half (16 MB)
__device__ float g_l[2 * NN];               // partial softmax denominators

// ---------------- helpers ----------------
// Fast exp via FMA-only range reduction + deg-4 poly + exponent splice.
// Used only in setup paths now. rel err ~4e-5. No MUFU.
__device__ __forceinline__ float fexp(float x) {
    float j = fmaf(x, 1.4426950408889634f, 12582912.0f);
    float n = j - 12582912.0f;
    float f = fmaf(n, -0.693359375f, x);
    f = fmaf(n, 2.1219444e-4f, f);
    float r = fmaf(f, 0.041666668f, 0.16666667f);
    r = fmaf(r, f, 0.5f);
    r = fmaf(r, f, 1.0f);
    r = fmaf(r, f, 1.0f);
    int sc = __float_as_int(j) << 23;
    return __int_as_float(__float_as_int(r) + sc);
}

__device__ __forceinline__ void mma_f16(float* d, const unsigned* a,
                                        unsigned b0, unsigned b1) {
    asm volatile(
        "mma.sync.aligned.m16n8k16.row.col.f32.f16.f16.f32 "
        "{%0,%1,%2,%3}, {%4,%5,%6,%7}, {%8,%9}, {%0,%1,%2,%3};\n"
        : "+f"(d[0]), "+f"(d[1]), "+f"(d[2]), "+f"(d[3])
        : "r"(a[0]), "r"(a[1]), "r"(a[2]), "r"(a[3]), "r"(b0), "r"(b1));
}

__device__ __forceinline__ void ldsm_x4(unsigned& r0, unsigned& r1,
                                        unsigned& r2, unsigned& r3, uint32_t addr) {
    asm volatile("ldmatrix.sync.aligned.m8n8.x4.shared.b16 {%0,%1,%2,%3}, [%4];"
                 : "=r"(r0), "=r"(r1), "=r"(r2), "=r"(r3) : "r"(addr));
}

__device__ __forceinline__ void cp_async16(uint32_t saddr, const void* gptr) {
    asm volatile("cp.async.cg.shared.global [%0], [%1], 16;\n"
                 :: "r"(saddr), "l"(gptr));
}
#define CP_COMMIT() asm volatile("cp.async.commit_group;\n" ::: "memory")
#define CP_WAIT(N)  asm volatile("cp.async.wait_group %0;\n" :: "n"(N) : "memory")

// monotone key: unsigned order == float order
__device__ __forceinline__ unsigned f2key(float x) {
    unsigned u = __float_as_uint(x);
    return ((int)u >= 0) ? (u | 0x80000000u) : ~u;
}

// ---------------- kernel 0: convert x, W to fp16 ----------------
__global__ __launch_bounds__(256) void k_cvt(const float* __restrict__ x,
                                             const float* __restrict__ W) {
    int b = blockIdx.x;
    const float* src;
    __half* dst;
    size_t v;
    if (b < 4096) { src = x; dst = g_xh; v = (size_t)b * 256 + threadIdx.x; }
    else          { src = W; dst = g_wh; v = (size_t)(b - 4096) * 256 + threadIdx.x; }
    float4 f = __ldg((const float4*)src + v);
    union { __half2 h[2]; uint2 u; } pk;
    pk.h[0] = __floats2half2_rn(f.x, f.y);
    pk.h[1] = __floats2half2_rn(f.z, f.w);
    *(uint2*)&dst[v * 4] = pk.u;
}

// ---------------- kernel 1: hT = W @ x^T via fp16 mma + cp.async pipeline -----
#define KH_S 72
#define KH_BUF (128 * KH_S)
#define KH_SMEM_BYTES (4 * KH_BUF * 2)       // 73728
__global__ __launch_bounds__(512) void k_h() {
    extern __shared__ __align__(16) __half kh_sm[];
    __half* sW = kh_sm;
    __half* sX = kh_sm + 2 * KH_BUF;
    const int tid = threadIdx.x;
    const int lane = tid & 31, w = tid >> 5;
    const int wm = w >> 2, wn = w & 3;
    const int g = lane >> 2, tq = lane & 3;
    const int n0 = blockIdx.x * 128, j0 = blockIdx.y * 128;
    const uint32_t swb = (uint32_t)__cvta_generic_to_shared(sW);
    const uint32_t sxb = (uint32_t)__cvta_generic_to_shared(sX);

    float acc[2][4][4];
#pragma unroll
    for (int mt = 0; mt < 2; mt++)
#pragma unroll
        for (int jb = 0; jb < 4; jb++)
#pragma unroll
            for (int q = 0; q < 4; q++) acc[mt][jb][q] = 0.0f;

    const int aoff = (wm * 32 + (lane & 15)) * KH_S + (lane >> 4) * 8;
    const int boff = (wn * 32 + (lane & 7) + ((lane & 16) ? 8 : 0)) * KH_S +
                     ((lane >> 3) & 1) * 8;

    auto issue = [&](int c) {
        int k0 = c * 64;
        int bsel = (c & 1) * KH_BUF;
#pragma unroll
        for (int q = 0; q < 2; q++) {
            int v = tid + q * 512;
            int r = v >> 3, ck = (v & 7) << 3;
            cp_async16(swb + (bsel + r * KH_S + ck) * 2,
                       g_wh + (size_t)(n0 + r) * DIN + k0 + ck);
            cp_async16(sxb + (bsel + r * KH_S + ck) * 2,
                       g_xh + (size_t)(j0 + r) * DIN + k0 + ck);
        }
    };

    issue(0); CP_COMMIT();
    for (int c = 0; c < 8; c++) {
        __syncthreads();
        if (c < 7) { issue(c + 1); CP_COMMIT(); }
        if (c < 7) { CP_WAIT(1); } else { CP_WAIT(0); }
        __syncthreads();
        const uint32_t aB = swb + ((c & 1) * KH_BUF + aoff) * 2;
        const uint32_t bB = sxb + ((c & 1) * KH_BUF + boff) * 2;
#pragma unroll
        for (int ks = 0; ks < 4; ks++) {
            unsigned A0[4], A1[4];
            ldsm_x4(A0[0], A0[1], A0[2], A0[3], aB + (ks * 16) * 2);
            ldsm_x4(A1[0], A1[1], A1[2], A1[3], aB + (16 * KH_S + ks * 16) * 2);
#pragma unroll
            for (int jp = 0; jp < 2; jp++) {
                unsigned B[4];
                ldsm_x4(B[0], B[1], B[2], B[3], bB + (jp * 16 * KH_S + ks * 16) * 2);
                mma_f16(acc[0][2 * jp], A0, B[0], B[1]);
                mma_f16(acc[0][2 * jp + 1], A0, B[2], B[3]);
                mma_f16(acc[1][2 * jp], A1, B[0], B[1]);
                mma_f16(acc[1][2 * jp + 1], A1, B[2], B[3]);
            }
        }
    }
#pragma unroll
    for (int mt = 0; mt < 2; mt++) {
        int n = n0 + wm * 32 + mt * 16 + g;
#pragma unroll
        for (int jb = 0; jb < 4; jb++) {
            int j = j0 + wn * 32 + jb * 8 + 2 * tq;
            *(__half2*)&g_hT[(size_t)n * NN + j] =
                __floats2half2_rn(acc[mt][jb][0], acc[mt][jb][1]);
            *(__half2*)&g_hT[(size_t)(n + 8) * NN + j] =
                __floats2half2_rn(acc[mt][jb][2], acc[mt][jb][3]);
        }
    }
}

// ---------------- kernel 2a: b1 = W^T a1, b2 = W^T a2; init m2key -------------
__global__ __launch_bounds__(512) void k_vec(const float* __restrict__ W,
                                             const float* __restrict__ a1,
                                             const float* __restrict__ a2) {
    __shared__ float as[DOUT];
    const float* a = blockIdx.x ? a2 : a1;
    float* out = blockIdx.x ? g_b2 : g_b1;
    int tid = threadIdx.x;
    if (blockIdx.x == 0 && tid == 0) g_m2key = 0u;   // reset (graph replays)
    if (tid < DOUT) as[tid] = a[tid];
    __syncthreads();
    float s = 0.0f;
#pragma unroll 16
    for (int i = 0; i < DOUT; i++)
        s = fmaf(__ldg(W + (size_t)i * DIN + tid), as[i], s);
    out[tid] = s;
}

// ---------------- kernel 2b: f1/f2 (fp32) + u=exp(f2), v=exp(.01 f2) + max ----
__global__ __launch_bounds__(256) void k_f12(const float* __restrict__ x) {
    __shared__ float b1s[DIN], b2s[DIN];
    __shared__ float mx[8];
    int tid = threadIdx.x;
    b1s[tid] = g_b1[tid]; b1s[tid + 256] = g_b1[tid + 256];
    b2s[tid] = g_b2[tid]; b2s[tid + 256] = g_b2[tid + 256];
    __syncthreads();
    int w = tid >> 5, lane = tid & 31;
    int row = blockIdx.x * 8 + w;
    const float* xr = x + (size_t)row * DIN;
    float s1 = 0.0f, s2 = 0.0f;
#pragma unroll
    for (int q = 0; q < 4; q++) {
        float4 xv = __ldg((const float4*)(xr + q * 128 + lane * 4));
        int c = q * 128 + lane * 4;
        s1 = fmaf(xv.x, b1s[c], fmaf(xv.y, b1s[c + 1],
             fmaf(xv.z, b1s[c + 2], fmaf(xv.w, b1s[c + 3], s1))));
        s2 = fmaf(xv.x, b2s[c], fmaf(xv.y, b2s[c + 1],
             fmaf(xv.z, b2s[c + 2], fmaf(xv.w, b2s[c + 3], s2))));
    }
#pragma unroll
    for (int off = 16; off >= 1; off >>= 1) {
        s1 += __shfl_xor_sync(0xffffffffu, s1, off);
        s2 += __shfl_xor_sync(0xffffffffu, s2, off);
    }
    if (lane == 0) {
        g_f1[row] = s1; g_f2[row] = s2;
        g_u[row] = fexp(s2);                 // exp(f2) <= e^~20, fp32-safe
        g_v[row] = fexp(0.01f * s2);
        mx[w] = s2;
    }
    __syncthreads();
    if (tid == 0) {
        float m = mx[0];
#pragma unroll
        for (int i = 1; i < 8; i++) m = fmaxf(m, mx[i]);
        atomicMax(&g_m2key, f2key(m));       // order-independent -> deterministic
    }
}

// ---------------- kernel 3: fused softmax-numerator @ h -----------------------
// Rank-1 factored P: p = adj * (z>=0 ? a_i*u_j : b_i*v_j), z = f1_i + f2_j,
// a_i = exp(f1_i - c_i), b_i = exp(0.01 f1_i - c_i), c_i = lrelu(f1_i + m2).
// p in (0,1] -> fp16-safe; NO exp in the hot loop. adj prefetched across the
// barrier so its DRAM latency hides behind the MMA phase.
#define SPH 136
#define SP_HALFS   (128 * SPH)
#define SHT_HALFS  (256 * SPH)
#define F1_BYTEOFF (4 * SP_HALFS + 4 * SHT_HALFS)
#define SMEM_BYTES (F1_BYTEOFF + 3 * 512 + 128)     // f1s, sA, sB
__global__ __launch_bounds__(512, 1) void k_attn(const float* __restrict__ adj) {
    extern __shared__ __align__(16) __half smh[];
    float* f1s = (float*)((char*)smh + F1_BYTEOFF);
    float* sA  = f1s + 128;
    float* sB  = f1s + 256;

    const int tid = threadIdx.x;
    const int jh = blockIdx.x, rb = blockIdx.y;
    const int lane = tid & 31, w = tid >> 5;
    const int wm = w >> 2, wn = w & 3;
    const int g = lane >> 2, tq = lane & 3;

    unsigned mk = g_m2key;
    const float m2 = (mk & 0x80000000u) ? __uint_as_float(mk & 0x7FFFFFFFu)
                                        : __uint_as_float(~mk);
    if (tid < 128) {
        float f1 = g_f1[rb * 128 + tid];
        float zc = f1 + m2;
        float c = fmaxf(zc, 0.01f * zc);     // row shift (same both halves)
        f1s[tid] = f1;
        sA[tid] = fexp(f1 - c);
        sB[tid] = fexp(fmaf(0.01f, f1, -c));
    }
    __syncthreads();

    float acc[2][8][4];
#pragma unroll
    for (int mt = 0; mt < 2; mt++)
#pragma unroll
        for (int nb = 0; nb < 8; nb++)
#pragma unroll
            for (int q = 0; q < 4; q++) acc[mt][nb][q] = 0.0f;

    float lacc[8];
#pragma unroll
    for (int i = 0; i < 8; i++) lacc[i] = 0.0f;

    const float* adjb = adj + (size_t)(rb * 128) * NN;
    const uint32_t smbase = (uint32_t)__cvta_generic_to_shared(smh);

    const int aoff = (wm * 32 + (lane & 15)) * SPH + (lane >> 4) * 8;
    const int boff = (wn * 64 + (lane & 7) + ((lane & 16) ? 8 : 0)) * SPH +
                     ((lane >> 3) & 1) * 8;

    // preload adj for tile 0
    float4 avp[8];
    {
        const int j0 = jh * 4096;
#pragma unroll
        for (int i = 0; i < 8; i++)
            avp[i] = __ldg((const float4*)(adjb + (size_t)(w + 16 * i) * NN + j0 + 4 * lane));
    }

    for (int jt = 0; jt < 32; jt++) {
        const int b = jt & 1;
        const int j0 = jh * 4096 + jt * 128;
        __half* sP = smh + b * SP_HALFS;
        const uint32_t sht_b = smbase + (2 * SP_HALFS + b * SHT_HALFS) * 2;

        // ---- stage H tile via cp.async ----
        {
            const __half* hsrc = g_hT + j0;
#pragma unroll
            for (int i = 0; i < 8; i++) {
                int v = tid + i * 512;
                int n = v >> 4;
                int c = (v & 15) << 3;
                cp_async16(sht_b + (n * SPH + c) * 2, hsrc + (size_t)n * NN + c);
            }
            CP_COMMIT();
        }

        // ---- P tile from rank-1 factors (no exp) ----
        float4 f2v = __ldg((const float4*)(g_f2 + j0 + 4 * lane));
        float4 uv  = __ldg((const float4*)(g_u  + j0 + 4 * lane));
        float4 vv  = __ldg((const float4*)(g_v  + j0 + 4 * lane));
#pragma unroll
        for (int i = 0; i < 8; i++) {
            int r = w + 16 * i;
            float f1v = f1s[r], ai = sA[r], bi = sB[r];
            float p0 = ((f1v + f2v.x >= 0.0f) ? ai * uv.x : bi * vv.x) * avp[i].x;
            float p1 = ((f1v + f2v.y >= 0.0f) ? ai * uv.y : bi * vv.y) * avp[i].y;
            float p2 = ((f1v + f2v.z >= 0.0f) ? ai * uv.z : bi * vv.z) * avp[i].z;
            float p3 = ((f1v + f2v.w >= 0.0f) ? ai * uv.w : bi * vv.w) * avp[i].w;
            __half2 h01 = __floats2half2_rn(p0, p1);
            __half2 h23 = __floats2half2_rn(p2, p3);
            union { __half2 h2[2]; uint2 u; } pk;
            pk.h2[0] = h01; pk.h2[1] = h23;
            *(uint2*)&sP[r * SPH + 4 * lane] = pk.u;
            float2 q01 = __half22float2(h01);    // sum fp16-ROUNDED values
            float2 q23 = __half22float2(h23);
            lacc[i] += (q01.x + q01.y) + (q23.x + q23.y);
        }

        // ---- prefetch adj for next tile (hides DRAM latency behind MMA) ----
        {
            const int jtn = (jt < 31) ? jt + 1 : 31;
            const int j0n = jh * 4096 + jtn * 128;
#pragma unroll
            for (int i = 0; i < 8; i++)
                avp[i] = __ldg((const float4*)(adjb + (size_t)(w + 16 * i) * NN + j0n + 4 * lane));
        }
        CP_WAIT(0);
        __syncthreads();

        // ---- mma via ldmatrix.x4: acc += P[128x128] @ H[128x256] ----
        const uint32_t aB = smbase + (b * SP_HALFS + aoff) * 2;
        const uint32_t bB = smbase + (2 * SP_HALFS + b * SHT_HALFS + boff) * 2;
#pragma unroll
        for (int kc = 0; kc < 8; kc++) {
            unsigned A0[4], A1[4];
            ldsm_x4(A0[0], A0[1], A0[2], A0[3], aB + (kc * 16) * 2);
            ldsm_x4(A1[0], A1[1], A1[2], A1[3], aB + (16 * SPH + kc * 16) * 2);
#pragma unroll
            for (int np = 0; np < 4; np++) {
                unsigned B[4];
                ldsm_x4(B[0], B[1], B[2], B[3], bB + (np * 16 * SPH + kc * 16) * 2);
                mma_f16(acc[0][2 * np], A0, B[0], B[1]);
                mma_f16(acc[0][2 * np + 1], A0, B[2], B[3]);
                mma_f16(acc[1][2 * np], A1, B[0], B[1]);
                mma_f16(acc[1][2 * np + 1], A1, B[2], B[3]);
            }
        }
    }

    // ---- final row-sum reduce + store partial l ----
#pragma unroll
    for (int i = 0; i < 8; i++) {
        float s = lacc[i];
#pragma unroll
        for (int off = 16; off >= 1; off >>= 1)
            s += __shfl_xor_sync(0xffffffffu, s, off);
        if (lane == 0) g_l[jh * NN + rb * 128 + w + 16 * i] = s;
    }

    // ---- epilogue: partial O ----
    float* Op = g_O + (size_t)jh * NN * DOUT;
#pragma unroll
    for (int mt = 0; mt < 2; mt++) {
        int row0 = rb * 128 + wm * 32 + mt * 16 + g;
#pragma unroll
        for (int nb = 0; nb < 8; nb++) {
            int col = wn * 64 + nb * 8 + tq * 2;
            *(float2*)&Op[(size_t)row0 * DOUT + col] =
                make_float2(acc[mt][nb][0], acc[mt][nb][1]);
            *(float2*)&Op[(size_t)(row0 + 8) * DOUT + col] =
                make_float2(acc[mt][nb][2], acc[mt][nb][3]);
        }
    }
}

// ---------------- kernel 4: combine halves, divide, elu ----------------
__global__ __launch_bounds__(256) void k_out(float* __restrict__ out) {
    int idx = blockIdx.x * 256 + threadIdx.x;
    int row = idx >> 8;
    float linv = 1.0f / (g_l[row] + g_l[NN + row]);
    float o = (g_O[idx] + g_O[NN * DOUT + idx]) * linv;
    out[idx] = (o > 0.0f) ? o : expm1f(o);
}

// ---------------- launch ----------------
extern "C" void kernel_launch(void* const* d_in, const int* in_sizes, int n_in,
                              void* d_out, int out_size) {
    const float* x   = (const float*)d_in[0];   // [8192, 512]
    const float* adj = (const float*)d_in[1];   // [8192, 8192]
    const float* W   = (const float*)d_in[2];   // [256, 512]
    const float* a1  = (const float*)d_in[3];   // [256]
    const float* a2  = (const float*)d_in[4];   // [256]
    float* out = (float*)d_out;                 // [8192, 256]

    (void)in_sizes; (void)n_in; (void)out_size;
    cudaFuncSetAttribute(k_attn, cudaFuncAttributeMaxDynamicSharedMemorySize,
                         SMEM_BYTES);
    cudaFuncSetAttribute(k_h, cudaFuncAttributeMaxDynamicSharedMemorySize,
                         KH_SMEM_BYTES);

    k_cvt<<<4224, 256>>>(x, W);
    k_h<<<dim3(2, 64), 512, KH_SMEM_BYTES>>>();
    k_vec<<<2, 512>>>(W, a1, a2);
    k_f12<<<NN / 8, 256>>>(x);
    k_attn<<<dim3(2, 64), 512, SMEM_BYTES>>>(adj);
    k_out<<<(NN * DOUT) / 256, 256>>>(out);
}